// round 13
// baseline (speedup 1.0000x reference)
#include <cuda_runtime.h>
#include <cuda_fp16.h>
#include <cstdint>
#include <math.h>

#define CC    1024
#define MM    8192
#define MIMG  2048
#define FFD   4096

// ---------------------------------------------------------------------------
// helpers
// ---------------------------------------------------------------------------
__device__ __forceinline__ uint32_t smem_u32(const void* p) {
    uint32_t a;
    asm("{ .reg .u64 t; cvta.to.shared.u64 t, %1; cvt.u32.u64 %0, t; }" : "=r"(a) : "l"(p));
    return a;
}
__device__ __forceinline__ void ldsm4(uint32_t a, uint32_t& r0, uint32_t& r1,
                                      uint32_t& r2, uint32_t& r3) {
    asm volatile("ldmatrix.sync.aligned.m8n8.x4.shared.b16 {%0,%1,%2,%3}, [%4];"
                 : "=r"(r0), "=r"(r1), "=r"(r2), "=r"(r3) : "r"(a));
}
__device__ __forceinline__ void ldsm4t(uint32_t a, uint32_t& r0, uint32_t& r1,
                                       uint32_t& r2, uint32_t& r3) {
    asm volatile("ldmatrix.sync.aligned.m8n8.x4.trans.shared.b16 {%0,%1,%2,%3}, [%4];"
                 : "=r"(r0), "=r"(r1), "=r"(r2), "=r"(r3) : "r"(a));
}
__device__ __forceinline__ void mma_f16(float* c, const uint32_t* a, uint32_t b0, uint32_t b1) {
    asm volatile("mma.sync.aligned.m16n8k16.row.col.f32.f16.f16.f32 "
                 "{%0,%1,%2,%3}, {%4,%5,%6,%7}, {%8,%9}, {%0,%1,%2,%3};"
                 : "+f"(c[0]), "+f"(c[1]), "+f"(c[2]), "+f"(c[3])
                 : "r"(a[0]), "r"(a[1]), "r"(a[2]), "r"(a[3]), "r"(b0), "r"(b1));
}
__device__ __forceinline__ void cp16(uint32_t dst, const void* src) {
    asm volatile("cp.async.cg.shared.global [%0], [%1], 16;" :: "r"(dst), "l"(src));
}
__device__ __forceinline__ uint32_t pack2(__half a, __half b) {
    __half2 t = __halves2half2(a, b);
    return *reinterpret_cast<uint32_t*>(&t);
}
__device__ __forceinline__ float gelu_tanh(float x) {
    float u = 0.7978845608028654f * (x + 0.044715f * x * x * x);
    return 0.5f * x * (1.0f + tanhf(u));
}
// MUFU-free exp: exp(x) = 2^(x*log2e), poly on fractional part (FMA pipe only).
// rel err ~8e-5, valid for x <= ~0 (softmax use). Handles -1e30 via clamp.
__device__ __forceinline__ float fexp(float x) {
    x = fmaxf(x * 1.4426950408889634f, -126.0f);
    float fl = floorf(x);
    float y = x - fl;
    float p = fmaf(y, 0.0013333558f, 0.0096181291f);
    p = fmaf(p, y, 0.0555041087f);
    p = fmaf(p, y, 0.2402265069f);
    p = fmaf(p, y, 0.6931471806f);
    p = fmaf(p, y, 1.0f);
    return __uint_as_float((uint32_t)((int)fl + 127) << 23) * p;
}

// ---------------------------------------------------------------------------
// Scratch
// ---------------------------------------------------------------------------
__device__ __half g_wt[16777216];          // transposed fp16 weights [N,K]
__device__ __half g_qkv[MM * 3 * CC];
__device__ __half g_q[MM * CC];
__device__ __half g_kv[MIMG * 2 * CC];
__device__ __half g_a[MM * CC];
__device__ __half g_ff[MM * FFD];
__device__ __half g_xi[MIMG * CC];
__device__ float g_bkv[2 * CC];

#define OFF_ATTN  0u
#define OFF_APROJ 3145728u
#define OFF_Q     4194304u
#define OFF_K     5242880u
#define OFF_V     6291456u
#define OFF_CPROJ 7340032u
#define OFF_FC    8388608u
#define OFF_MPROJ 12582912u

// ---------------------------------------------------------------------------
// batched transpose+cast: all 8 weights in ONE launch.
// ---------------------------------------------------------------------------
struct PrepDesc {
    const float* W;
    uint32_t dstOff;
    int K, N;
    int tiles;
};
struct Prep8 { PrepDesc d[8]; };

__global__ __launch_bounds__(256) void prep_weights_kernel(Prep8 p, __half* dstBase)
{
    __shared__ float t[32][33];
    int bid = blockIdx.x;
    int di = 0;
    #pragma unroll
    for (int i = 0; i < 7; i++)
        if (bid >= p.d[di].tiles) { bid -= p.d[di].tiles; di++; }
    const PrepDesc& d = p.d[di];
    const int ntiles_n = d.N >> 5;
    const int n0 = (bid % ntiles_n) * 32;
    const int k0 = (bid / ntiles_n) * 32;
    {
        const int tx = threadIdx.x & 31, ty = threadIdx.x >> 5;
        #pragma unroll
        for (int i = 0; i < 4; i++) {
            int kk = ty + i * 8;
            t[kk][tx] = d.W[(size_t)(k0 + kk) * d.N + n0 + tx];
        }
    }
    __syncthreads();
    __half* dst = dstBase + d.dstOff;
    const int kp = threadIdx.x & 15;
    const int nyb = threadIdx.x >> 4;
    #pragma unroll
    for (int i = 0; i < 2; i++) {
        int nn = nyb + i * 16;
        uint32_t v = pack2(__float2half(t[2*kp][nn]), __float2half(t[2*kp+1][nn]));
        *(uint32_t*)(dst + (size_t)(n0 + nn) * d.K + k0 + 2*kp) = v;
    }
}

__global__ void tofp16_kernel(const float* __restrict__ x,
                              __half* __restrict__ o, int n)
{
    int i = blockIdx.x * blockDim.x + threadIdx.x;
    if (i < n) o[i] = __float2half(x[i]);
}

__global__ void concat_bias_kernel(const float* __restrict__ a,
                                   const float* __restrict__ b,
                                   float* __restrict__ o)
{
    int i = blockIdx.x * blockDim.x + threadIdx.x;
    if (i < CC) o[i] = a[i];
    else if (i < 2 * CC) o[i] = b[i - CC];
}

// ---------------------------------------------------------------------------
// single-pass pair reduction + LayerNorm (fp16 output)
// ---------------------------------------------------------------------------
__device__ __forceinline__ float2 block_sum2(float a, float b) {
    __shared__ float2 red[8];
    int lane = threadIdx.x & 31;
    int w    = threadIdx.x >> 5;
    #pragma unroll
    for (int o = 16; o; o >>= 1) {
        a += __shfl_xor_sync(0xffffffffu, a, o);
        b += __shfl_xor_sync(0xffffffffu, b, o);
    }
    if (lane == 0) red[w] = make_float2(a, b);
    __syncthreads();
    if (w == 0) {
        float2 v = (lane < 8) ? red[lane] : make_float2(0.f, 0.f);
        #pragma unroll
        for (int o = 4; o; o >>= 1) {
            v.x += __shfl_xor_sync(0xffffffffu, v.x, o);
            v.y += __shfl_xor_sync(0xffffffffu, v.y, o);
        }
        if (lane == 0) red[0] = v;
    }
    __syncthreads();
    return red[0];
}

__global__ __launch_bounds__(256) void ln_h_kernel(
    const float* __restrict__ in, const float* __restrict__ g,
    const float* __restrict__ b, __half* __restrict__ out)
{
    const int row = blockIdx.x;
    const float4 v = ((const float4*)(in + (size_t)row * CC))[threadIdx.x];
    float s = v.x + v.y + v.z + v.w;
    float q = v.x*v.x + v.y*v.y + v.z*v.z + v.w*v.w;
    float2 r = block_sum2(s, q);
    const float mean = r.x * (1.0f / CC);
    const float var  = r.y * (1.0f / CC) - mean * mean;
    const float rstd = rsqrtf(var + 1e-5f);
    const float4 gg = ((const float4*)g)[threadIdx.x];
    const float4 bb = ((const float4*)b)[threadIdx.x];
    __half h0 = __float2half((v.x - mean) * rstd * gg.x + bb.x);
    __half h1 = __float2half((v.y - mean) * rstd * gg.y + bb.y);
    __half h2 = __float2half((v.z - mean) * rstd * gg.z + bb.z);
    __half h3 = __float2half((v.w - mean) * rstd * gg.w + bb.w);
    size_t off = (size_t)row * CC + threadIdx.x * 4;
    *(uint2*)(out + off) = make_uint2(pack2(h0,h1), pack2(h2,h3));
}

// ---------------------------------------------------------------------------
// HMMA fp16 single-pass GEMM (unchanged from R12)
// ---------------------------------------------------------------------------
#define GRS 72
#define ATB (128 * GRS * 2)
#define BTB (256 * GRS * 2)
#define GSTAGE (ATB + BTB)
#define GEMM_SMEM (3 * GSTAGE)

template<int OMODE, bool GELU>
__global__ __launch_bounds__(256, 1) void mma_gemm(
    const __half* __restrict__ Ah, const __half* __restrict__ Bh,
    const float* __restrict__ bias, const float* __restrict__ res,
    float* __restrict__ outf, __half* __restrict__ outh,
    int M, int N, int K)
{
    extern __shared__ __align__(16) char smem[];
    const uint32_t base = smem_u32(smem);
    const int tid = threadIdx.x;
    const int wid = tid >> 5, lane = tid & 31;
    const int wm = wid >> 2, wn = wid & 3;
    const int m0 = blockIdx.y * 128, n0 = blockIdx.x * 256;

    const __half* gA = Ah + (size_t)m0 * K;
    const __half* gB = Bh + (size_t)n0 * K;

    auto stage = [&](int k0, int buf) {
        const uint32_t sb = base + buf * GSTAGE;
        #pragma unroll
        for (int i = 0; i < 4; i++) {
            int idx = tid + i * 256;
            int r = idx >> 3, s = idx & 7;
            cp16(sb + (r * GRS + s * 8) * 2, gA + (size_t)r * K + k0 + s * 8);
        }
        #pragma unroll
        for (int i = 0; i < 8; i++) {
            int idx = tid + i * 256;
            int r = idx >> 3, s = idx & 7;
            cp16(sb + ATB + (r * GRS + s * 8) * 2, gB + (size_t)r * K + k0 + s * 8);
        }
        asm volatile("cp.async.commit_group;");
    };

    const int laRowA = ((lane >> 3) & 1) * 8 + (lane & 7);
    const int laColA = (lane >> 4) * 8;
    const int laRowB = ((lane >> 4) << 3) + (lane & 7);
    const int laColB = ((lane >> 3) & 1) * 8;

    float c[4][8][4];
    #pragma unroll
    for (int i = 0; i < 4; i++)
        #pragma unroll
        for (int j = 0; j < 8; j++)
            #pragma unroll
            for (int q = 0; q < 4; q++) c[i][j][q] = 0.f;

    const int nch = K >> 6;
    stage(0, 0);
    stage(64, 1);

    for (int ch = 0; ch < nch; ch++) {
        if (ch + 1 < nch) asm volatile("cp.async.wait_group 1;");
        else              asm volatile("cp.async.wait_group 0;");
        __syncthreads();
        if (ch + 2 < nch) stage((ch + 2) << 6, (ch + 2) % 3);

        const uint32_t sb = base + (ch % 3) * GSTAGE;
        const uint32_t sA = sb, sB = sb + ATB;

        #pragma unroll
        for (int ks = 0; ks < 64; ks += 16) {
            uint32_t a[4][4];
            #pragma unroll
            for (int mf = 0; mf < 4; mf++) {
                uint32_t off = ((wm * 64 + mf * 16 + laRowA) * GRS + ks + laColA) * 2;
                ldsm4(sA + off, a[mf][0], a[mf][1], a[mf][2], a[mf][3]);
            }
            uint32_t bh[8][2];
            #pragma unroll
            for (int np = 0; np < 4; np++) {
                uint32_t off = ((wn * 64 + np * 16 + laRowB) * GRS + ks + laColB) * 2;
                ldsm4(sB + off, bh[2*np][0], bh[2*np][1], bh[2*np+1][0], bh[2*np+1][1]);
            }
            #pragma unroll
            for (int mf = 0; mf < 4; mf++)
                #pragma unroll
                for (int nf = 0; nf < 8; nf++)
                    mma_f16(c[mf][nf], a[mf], bh[nf][0], bh[nf][1]);
        }
    }

    #pragma unroll
    for (int mf = 0; mf < 4; mf++) {
        const int rbase = m0 + wm * 64 + mf * 16 + (lane >> 2);
        #pragma unroll
        for (int nf = 0; nf < 8; nf++) {
            const int gn = n0 + wn * 64 + nf * 8 + (lane & 3) * 2;
            const float2 b2 = *(const float2*)(bias + gn);
            #pragma unroll
            for (int half_ = 0; half_ < 2; half_++) {
                const int gm = rbase + half_ * 8;
                float v0 = c[mf][nf][half_ * 2 + 0] + b2.x;
                float v1 = c[mf][nf][half_ * 2 + 1] + b2.y;
                if (GELU) { v0 = gelu_tanh(v0); v1 = gelu_tanh(v1); }
                if (OMODE == 0) {
                    if (res) {
                        const float2 r2 = *(const float2*)(res + (size_t)gm * N + gn);
                        v0 += r2.x; v1 += r2.y;
                    }
                    *(float2*)(outf + (size_t)gm * N + gn) = make_float2(v0, v1);
                } else {
                    *(uint32_t*)(outh + (size_t)gm * N + gn) =
                        pack2(__float2half(v0), __float2half(v1));
                }
            }
        }
    }
}

// ---------------------------------------------------------------------------
// Flash attention, fp16 single-pass, MUFU-free softmax exp.
// ---------------------------------------------------------------------------
#define FRS 72
#define QTB (128 * FRS * 2)
#define KVT (64 * FRS * 2)
#define KVSTAGE (2 * KVT)
#define FLASH_SMEM (QTB + 2 * KVSTAGE)

template<bool CAUSAL>
__global__ __launch_bounds__(256, 1) void flash_mma(
    const __half* __restrict__ Qh,
    const __half* __restrict__ Kh, const __half* __restrict__ Vh,
    __half* __restrict__ Ohi,
    int Tq, int Tkv, int qS, int kS, float scale)
{
    extern __shared__ __align__(16) char smem[];
    const uint32_t base = smem_u32(smem);
    const uint32_t sQ = base;

    const int tid = threadIdx.x;
    const int wid = tid >> 5, lane = tid & 31;
    const int bh = blockIdx.y;
    const int b = bh >> 4, h = bh & 15;
    const int qt = blockIdx.x;

    const __half* Qb  = Qh + (size_t)(b * Tq + qt * 128) * qS + h * 64;
    const __half* Khb = Kh + (size_t)(b * Tkv) * kS + h * 64;
    const __half* Vhb = Vh + (size_t)(b * Tkv) * kS + h * 64;

    auto stage_kv = [&](int kt, int buf) {
        const uint32_t sb = base + QTB + buf * KVSTAGE;
        #pragma unroll
        for (int i = 0; i < 2; i++) {
            int idx = tid + i * 256;
            int r = idx >> 3, s = idx & 7;
            size_t go = (size_t)(kt * 64 + r) * kS + s * 8;
            uint32_t off = (r * FRS + s * 8) * 2;
            cp16(sb + 0 * KVT + off, Khb + go);
            cp16(sb + 1 * KVT + off, Vhb + go);
        }
        asm volatile("cp.async.commit_group;");
    };

    #pragma unroll
    for (int i = 0; i < 4; i++) {
        int idx = tid + i * 256;
        int r = idx >> 3, s = idx & 7;
        cp16(sQ + (r * FRS + s * 8) * 2, Qb + (size_t)r * qS + s * 8);
    }
    stage_kv(0, 0);

    const int laRowA = ((lane >> 3) & 1) * 8 + (lane & 7);
    const int laColA = (lane >> 4) * 8;
    const int laRowB = ((lane >> 4) << 3) + (lane & 7);
    const int laColB = ((lane >> 3) & 1) * 8;

    float o[8][4];
    #pragma unroll
    for (int i = 0; i < 8; i++)
        #pragma unroll
        for (int j = 0; j < 4; j++) o[i][j] = 0.f;
    float mr0 = -1e30f, mr1 = -1e30f, lr0 = 0.f, lr1 = 0.f;

    const int nkt = CAUSAL ? (2 * qt + 2) : (Tkv >> 6);

    for (int kt = 0; kt < nkt; kt++) {
        if (kt + 1 < nkt) {
            stage_kv(kt + 1, (kt + 1) & 1);
            asm volatile("cp.async.wait_group 1;");
        } else {
            asm volatile("cp.async.wait_group 0;");
        }
        __syncthreads();

        const uint32_t sb = base + QTB + (kt & 1) * KVSTAGE;
        const uint32_t sK = sb, sV = sb + KVT;

        float s[8][4];
        #pragma unroll
        for (int i = 0; i < 8; i++)
            #pragma unroll
            for (int j = 0; j < 4; j++) s[i][j] = 0.f;

        #pragma unroll
        for (int ks = 0; ks < 4; ks++) {
            uint32_t q[4];
            uint32_t qoff = ((wid * 16 + laRowA) * FRS + ks * 16 + laColA) * 2;
            ldsm4(sQ + qoff, q[0], q[1], q[2], q[3]);
            #pragma unroll
            for (int np = 0; np < 4; np++) {
                uint32_t koff = ((np * 16 + laRowB) * FRS + ks * 16 + laColB) * 2;
                uint32_t k0, k1, k2, k3;
                ldsm4(sK + koff, k0, k1, k2, k3);
                mma_f16(s[2*np],   q, k0, k1);
                mma_f16(s[2*np+1], q, k2, k3);
            }
        }
        #pragma unroll
        for (int i = 0; i < 8; i++)
            #pragma unroll
            for (int j = 0; j < 4; j++) s[i][j] *= scale;

        if (CAUSAL && kt >= 2 * qt) {
            const int row0 = qt * 128 + wid * 16 + (lane >> 2);
            #pragma unroll
            for (int nf = 0; nf < 8; nf++) {
                const int col = kt * 64 + nf * 8 + (lane & 3) * 2;
                if (col     > row0)     s[nf][0] = -1e30f;
                if (col + 1 > row0)     s[nf][1] = -1e30f;
                if (col     > row0 + 8) s[nf][2] = -1e30f;
                if (col + 1 > row0 + 8) s[nf][3] = -1e30f;
            }
        }

        float t0 = -1e30f, t1 = -1e30f;
        #pragma unroll
        for (int nf = 0; nf < 8; nf++) {
            t0 = fmaxf(t0, fmaxf(s[nf][0], s[nf][1]));
            t1 = fmaxf(t1, fmaxf(s[nf][2], s[nf][3]));
        }
        t0 = fmaxf(t0, __shfl_xor_sync(0xffffffffu, t0, 1));
        t0 = fmaxf(t0, __shfl_xor_sync(0xffffffffu, t0, 2));
        t1 = fmaxf(t1, __shfl_xor_sync(0xffffffffu, t1, 1));
        t1 = fmaxf(t1, __shfl_xor_sync(0xffffffffu, t1, 2));
        const float nm0 = fmaxf(mr0, t0), nm1 = fmaxf(mr1, t1);
        const float f0 = fexp(mr0 - nm0), f1 = fexp(mr1 - nm1);
        mr0 = nm0; mr1 = nm1;

        float rs0 = 0.f, rs1 = 0.f;
        #pragma unroll
        for (int nf = 0; nf < 8; nf++) {
            s[nf][0] = fexp(s[nf][0] - nm0);
            s[nf][1] = fexp(s[nf][1] - nm0);
            s[nf][2] = fexp(s[nf][2] - nm1);
            s[nf][3] = fexp(s[nf][3] - nm1);
            rs0 += s[nf][0] + s[nf][1];
            rs1 += s[nf][2] + s[nf][3];
        }
        rs0 += __shfl_xor_sync(0xffffffffu, rs0, 1);
        rs0 += __shfl_xor_sync(0xffffffffu, rs0, 2);
        rs1 += __shfl_xor_sync(0xffffffffu, rs1, 1);
        rs1 += __shfl_xor_sync(0xffffffffu, rs1, 2);
        lr0 = lr0 * f0 + rs0;
        lr1 = lr1 * f1 + rs1;
        #pragma unroll
        for (int nf = 0; nf < 8; nf++) {
            o[nf][0] *= f0; o[nf][1] *= f0;
            o[nf][2] *= f1; o[nf][3] *= f1;
        }

        uint32_t ph[4][4];
        #pragma unroll
        for (int j = 0; j < 4; j++) {
            ph[j][0] = pack2(__float2half(s[2*j][0]),   __float2half(s[2*j][1]));
            ph[j][1] = pack2(__float2half(s[2*j][2]),   __float2half(s[2*j][3]));
            ph[j][2] = pack2(__float2half(s[2*j+1][0]), __float2half(s[2*j+1][1]));
            ph[j][3] = pack2(__float2half(s[2*j+1][2]), __float2half(s[2*j+1][3]));
        }

        #pragma unroll
        for (int j = 0; j < 4; j++) {
            #pragma unroll
            for (int np = 0; np < 4; np++) {
                uint32_t voff = ((j * 16 + laRowA) * FRS + np * 16 + laColA) * 2;
                uint32_t v0, v1, v2, v3;
                ldsm4t(sV + voff, v0, v1, v2, v3);
                mma_f16(o[2*np],   ph[j], v0, v1);
                mma_f16(o[2*np+1], ph[j], v2, v3);
            }
        }
        __syncthreads();
    }

    const float inv0 = 1.0f / lr0, inv1 = 1.0f / lr1;
    const int row0 = qt * 128 + wid * 16 + (lane >> 2);
    #pragma unroll
    for (int nf = 0; nf < 8; nf++) {
        const int col = h * 64 + nf * 8 + (lane & 3) * 2;
        {
            size_t off = (size_t)(b * Tq + row0) * CC + col;
            *(uint32_t*)(Ohi + off) =
                pack2(__float2half(o[nf][0] * inv0), __float2half(o[nf][1] * inv0));
        }
        {
            size_t off = (size_t)(b * Tq + row0 + 8) * CC + col;
            *(uint32_t*)(Ohi + off) =
                pack2(__float2half(o[nf][2] * inv1), __float2half(o[nf][3] * inv1));
        }
    }
}

// ---------------------------------------------------------------------------
// Launch sequence
// ---------------------------------------------------------------------------
extern "C" void kernel_launch(void* const* d_in, const int* in_sizes, int n_in,
                              void* d_out, int out_size)
{
    (void)in_sizes; (void)n_in; (void)out_size;
    const float* x      = (const float*)d_in[0];
    const float* ximg   = (const float*)d_in[1];
    const float* ln1_g  = (const float*)d_in[2];
    const float* ln1_b  = (const float*)d_in[3];
    const float* ln2_g  = (const float*)d_in[4];
    const float* ln2_b  = (const float*)d_in[5];
    const float* W_attn = (const float*)d_in[6];
    const float* b_attn = (const float*)d_in[7];
    const float* W_aproj= (const float*)d_in[8];
    const float* b_aproj= (const float*)d_in[9];
    const float* Wq     = (const float*)d_in[10];
    const float* bq     = (const float*)d_in[11];
    const float* Wk     = (const float*)d_in[12];
    const float* bk     = (const float*)d_in[13];
    const float* Wv     = (const float*)d_in[14];
    const float* bv     = (const float*)d_in[15];
    const float* Wcproj = (const float*)d_in[16];
    const float* bcproj = (const float*)d_in[17];
    const float* W_fc   = (const float*)d_in[18];
    const float* b_fc   = (const float*)d_in[19];
    const float* W_mproj= (const float*)d_in[20];
    const float* b_mproj= (const float*)d_in[21];
    float* out = (float*)d_out;

    __half *wt, *qkv, *q, *kv, *a, *ff, *xi;
    float* bkv;
    cudaGetSymbolAddress((void**)&wt,  g_wt);
    cudaGetSymbolAddress((void**)&qkv, g_qkv);
    cudaGetSymbolAddress((void**)&q,   g_q);
    cudaGetSymbolAddress((void**)&kv,  g_kv);
    cudaGetSymbolAddress((void**)&a,   g_a);
    cudaGetSymbolAddress((void**)&ff,  g_ff);
    cudaGetSymbolAddress((void**)&xi,  g_xi);
    cudaGetSymbolAddress((void**)&bkv, g_bkv);

    cudaFuncSetAttribute(mma_gemm<0,false>, cudaFuncAttributeMaxDynamicSharedMemorySize, GEMM_SMEM);
    cudaFuncSetAttribute(mma_gemm<1,false>, cudaFuncAttributeMaxDynamicSharedMemorySize, GEMM_SMEM);
    cudaFuncSetAttribute(mma_gemm<1,true>,  cudaFuncAttributeMaxDynamicSharedMemorySize, GEMM_SMEM);
    cudaFuncSetAttribute(flash_mma<true>,  cudaFuncAttributeMaxDynamicSharedMemorySize, FLASH_SMEM);
    cudaFuncSetAttribute(flash_mma<false>, cudaFuncAttributeMaxDynamicSharedMemorySize, FLASH_SMEM);

    const float scale = 0.125f;

    // ---- prep ----
    tofp16_kernel<<<(MIMG*CC + 255)/256, 256>>>(ximg, xi, MIMG*CC);
    concat_bias_kernel<<<(2*CC + 255)/256, 256>>>(bk, bv, bkv);

    Prep8 pp;
    pp.d[0] = { W_attn,  OFF_ATTN,  CC, 3*CC, (3*CC/32)*(CC/32) };
    pp.d[1] = { W_aproj, OFF_APROJ, CC, CC,   (CC/32)*(CC/32)   };
    pp.d[2] = { Wq,      OFF_Q,     CC, CC,   (CC/32)*(CC/32)   };
    pp.d[3] = { Wk,      OFF_K,     CC, CC,   (CC/32)*(CC/32)   };
    pp.d[4] = { Wv,      OFF_V,     CC, CC,   (CC/32)*(CC/32)   };
    pp.d[5] = { Wcproj,  OFF_CPROJ, CC, CC,   (CC/32)*(CC/32)   };
    pp.d[6] = { W_fc,    OFF_FC,    CC, FFD,  (FFD/32)*(CC/32)  };
    pp.d[7] = { W_mproj, OFF_MPROJ, FFD, CC,  (CC/32)*(FFD/32)  };
    prep_weights_kernel<<<3072 + 5*1024 + 2*4096, 256>>>(pp, wt);

    // ---- causal self-attention ----
    ln_h_kernel<<<MM, 256>>>(x, ln1_g, ln1_b, a);
    mma_gemm<1,false><<<dim3(3*CC/256, MM/128), 256, GEMM_SMEM>>>(
        a, wt+OFF_ATTN, b_attn, nullptr, nullptr, qkv, MM, 3*CC, CC);
    flash_mma<true><<<dim3(8, 128), 256, FLASH_SMEM>>>(
        qkv, qkv + CC, qkv + 2*CC, a, 1024, 1024, 3*CC, 3*CC, scale);
    mma_gemm<0,false><<<dim3(CC/256, MM/128), 256, GEMM_SMEM>>>(
        a, wt+OFF_APROJ, b_aproj, x, out, nullptr, MM, CC, CC);

    // ---- cross-attention ----
    ln_h_kernel<<<MM, 256>>>(out, ln1_g, ln1_b, a);
    mma_gemm<1,false><<<dim3(CC/256, MM/128), 256, GEMM_SMEM>>>(
        a, wt+OFF_Q, bq, nullptr, nullptr, q, MM, CC, CC);
    mma_gemm<1,false><<<dim3(2*CC/256, MIMG/128), 256, GEMM_SMEM>>>(
        xi, wt+OFF_K, bkv, nullptr, nullptr, kv, MIMG, 2*CC, CC);
    flash_mma<false><<<dim3(8, 128), 256, FLASH_SMEM>>>(
        q, kv, kv + CC, a, 1024, 256, CC, 2*CC, scale);
    mma_gemm<0,false><<<dim3(CC/256, MM/128), 256, GEMM_SMEM>>>(
        a, wt+OFF_CPROJ, bcproj, out, out, nullptr, MM, CC, CC);

    // ---- MLP ----
    ln_h_kernel<<<MM, 256>>>(out, ln2_g, ln2_b, a);
    mma_gemm<1,true><<<dim3(FFD/256, MM/128), 256, GEMM_SMEM>>>(
        a, wt+OFF_FC, b_fc, nullptr, nullptr, ff, MM, FFD, CC);
    mma_gemm<0,false><<<dim3(CC/256, MM/128), 256, GEMM_SMEM>>>(
        ff, wt+OFF_MPROJ, b_mproj, out, out, nullptr, MM, CC, FFD);
}

// round 14
// speedup vs baseline: 1.0456x; 1.0456x over previous
#include <cuda_runtime.h>
#include <cuda_fp16.h>
#include <cstdint>
#include <math.h>

#define CC    1024
#define MM    8192
#define MIMG  2048
#define FFD   4096

// ---------------------------------------------------------------------------
// helpers
// ---------------------------------------------------------------------------
__device__ __forceinline__ uint32_t smem_u32(const void* p) {
    uint32_t a;
    asm("{ .reg .u64 t; cvta.to.shared.u64 t, %1; cvt.u32.u64 %0, t; }" : "=r"(a) : "l"(p));
    return a;
}
__device__ __forceinline__ void ldsm4(uint32_t a, uint32_t& r0, uint32_t& r1,
                                      uint32_t& r2, uint32_t& r3) {
    asm volatile("ldmatrix.sync.aligned.m8n8.x4.shared.b16 {%0,%1,%2,%3}, [%4];"
                 : "=r"(r0), "=r"(r1), "=r"(r2), "=r"(r3) : "r"(a));
}
__device__ __forceinline__ void ldsm4t(uint32_t a, uint32_t& r0, uint32_t& r1,
                                       uint32_t& r2, uint32_t& r3) {
    asm volatile("ldmatrix.sync.aligned.m8n8.x4.trans.shared.b16 {%0,%1,%2,%3}, [%4];"
                 : "=r"(r0), "=r"(r1), "=r"(r2), "=r"(r3) : "r"(a));
}
__device__ __forceinline__ void mma_f16(float* c, const uint32_t* a, uint32_t b0, uint32_t b1) {
    asm volatile("mma.sync.aligned.m16n8k16.row.col.f32.f16.f16.f32 "
                 "{%0,%1,%2,%3}, {%4,%5,%6,%7}, {%8,%9}, {%0,%1,%2,%3};"
                 : "+f"(c[0]), "+f"(c[1]), "+f"(c[2]), "+f"(c[3])
                 : "r"(a[0]), "r"(a[1]), "r"(a[2]), "r"(a[3]), "r"(b0), "r"(b1));
}
__device__ __forceinline__ void cp16(uint32_t dst, const void* src) {
    asm volatile("cp.async.cg.shared.global [%0], [%1], 16;" :: "r"(dst), "l"(src));
}
__device__ __forceinline__ uint32_t pack2(__half a, __half b) {
    __half2 t = __halves2half2(a, b);
    return *reinterpret_cast<uint32_t*>(&t);
}
__device__ __forceinline__ float htanh(float x) {
    float r;
    asm("tanh.approx.f32 %0, %1;" : "=f"(r) : "f"(x));
    return r;
}
__device__ __forceinline__ float gelu_tanh(float x) {
    float u = 0.7978845608028654f * (x + 0.044715f * x * x * x);
    return 0.5f * x * (1.0f + htanh(u));
}

// ---------------------------------------------------------------------------
// Scratch
// ---------------------------------------------------------------------------
__device__ __half g_wt[16777216];          // transposed fp16 weights [N,K]
__device__ __half g_qkv[MM * 3 * CC];
__device__ __half g_q[MM * CC];
__device__ __half g_kv[MIMG * 2 * CC];
__device__ __half g_a[MM * CC];
__device__ __half g_ff[MM * FFD];
__device__ __half g_xi[MIMG * CC];
__device__ float g_bkv[2 * CC];

#define OFF_ATTN  0u
#define OFF_APROJ 3145728u
#define OFF_Q     4194304u
#define OFF_K     5242880u
#define OFF_V     6291456u
#define OFF_CPROJ 7340032u
#define OFF_FC    8388608u
#define OFF_MPROJ 12582912u

// ---------------------------------------------------------------------------
// batched transpose+cast: all 8 weights in ONE launch.
// ---------------------------------------------------------------------------
struct PrepDesc {
    const float* W;
    uint32_t dstOff;
    int K, N;
    int tiles;
};
struct Prep8 { PrepDesc d[8]; };

__global__ __launch_bounds__(256) void prep_weights_kernel(Prep8 p, __half* dstBase)
{
    __shared__ float t[32][33];
    int bid = blockIdx.x;
    int di = 0;
    #pragma unroll
    for (int i = 0; i < 7; i++)
        if (bid >= p.d[di].tiles) { bid -= p.d[di].tiles; di++; }
    const PrepDesc& d = p.d[di];
    const int ntiles_n = d.N >> 5;
    const int n0 = (bid % ntiles_n) * 32;
    const int k0 = (bid / ntiles_n) * 32;
    {
        const int tx = threadIdx.x & 31, ty = threadIdx.x >> 5;
        #pragma unroll
        for (int i = 0; i < 4; i++) {
            int kk = ty + i * 8;
            t[kk][tx] = d.W[(size_t)(k0 + kk) * d.N + n0 + tx];
        }
    }
    __syncthreads();
    __half* dst = dstBase + d.dstOff;
    const int kp = threadIdx.x & 15;
    const int nyb = threadIdx.x >> 4;
    #pragma unroll
    for (int i = 0; i < 2; i++) {
        int nn = nyb + i * 16;
        uint32_t v = pack2(__float2half(t[2*kp][nn]), __float2half(t[2*kp+1][nn]));
        *(uint32_t*)(dst + (size_t)(n0 + nn) * d.K + k0 + 2*kp) = v;
    }
}

__global__ void tofp16_kernel(const float* __restrict__ x,
                              __half* __restrict__ o, int n)
{
    int i = blockIdx.x * blockDim.x + threadIdx.x;
    if (i < n) o[i] = __float2half(x[i]);
}

__global__ void concat_bias_kernel(const float* __restrict__ a,
                                   const float* __restrict__ b,
                                   float* __restrict__ o)
{
    int i = blockIdx.x * blockDim.x + threadIdx.x;
    if (i < CC) o[i] = a[i];
    else if (i < 2 * CC) o[i] = b[i - CC];
}

// ---------------------------------------------------------------------------
// single-pass pair reduction + LayerNorm (fp16 output)
// ---------------------------------------------------------------------------
__device__ __forceinline__ float2 block_sum2(float a, float b) {
    __shared__ float2 red[8];
    int lane = threadIdx.x & 31;
    int w    = threadIdx.x >> 5;
    #pragma unroll
    for (int o = 16; o; o >>= 1) {
        a += __shfl_xor_sync(0xffffffffu, a, o);
        b += __shfl_xor_sync(0xffffffffu, b, o);
    }
    if (lane == 0) red[w] = make_float2(a, b);
    __syncthreads();
    if (w == 0) {
        float2 v = (lane < 8) ? red[lane] : make_float2(0.f, 0.f);
        #pragma unroll
        for (int o = 4; o; o >>= 1) {
            v.x += __shfl_xor_sync(0xffffffffu, v.x, o);
            v.y += __shfl_xor_sync(0xffffffffu, v.y, o);
        }
        if (lane == 0) red[0] = v;
    }
    __syncthreads();
    return red[0];
}

__global__ __launch_bounds__(256) void ln_h_kernel(
    const float* __restrict__ in, const float* __restrict__ g,
    const float* __restrict__ b, __half* __restrict__ out)
{
    const int row = blockIdx.x;
    const float4 v = ((const float4*)(in + (size_t)row * CC))[threadIdx.x];
    float s = v.x + v.y + v.z + v.w;
    float q = v.x*v.x + v.y*v.y + v.z*v.z + v.w*v.w;
    float2 r = block_sum2(s, q);
    const float mean = r.x * (1.0f / CC);
    const float var  = r.y * (1.0f / CC) - mean * mean;
    const float rstd = rsqrtf(var + 1e-5f);
    const float4 gg = ((const float4*)g)[threadIdx.x];
    const float4 bb = ((const float4*)b)[threadIdx.x];
    __half h0 = __float2half((v.x - mean) * rstd * gg.x + bb.x);
    __half h1 = __float2half((v.y - mean) * rstd * gg.y + bb.y);
    __half h2 = __float2half((v.z - mean) * rstd * gg.z + bb.z);
    __half h3 = __float2half((v.w - mean) * rstd * gg.w + bb.w);
    size_t off = (size_t)row * CC + threadIdx.x * 4;
    *(uint2*)(out + off) = make_uint2(pack2(h0,h1), pack2(h2,h3));
}

// ---------------------------------------------------------------------------
// HMMA fp16 single-pass GEMM: out[M,N] = A[M,K] @ Wt[N,K]^T + bias
// Block 128x256x64; 8 warps 2(M)x4(N); warp tile 64x64; 3-stage cp.async.
// OMODE: 0 = fp32 out (+res), 1 = fp16 out
// ---------------------------------------------------------------------------
#define GRS 72
#define ATB (128 * GRS * 2)
#define BTB (256 * GRS * 2)
#define GSTAGE (ATB + BTB)
#define GEMM_SMEM (3 * GSTAGE)

template<int OMODE, bool GELU>
__global__ __launch_bounds__(256, 1) void mma_gemm(
    const __half* __restrict__ Ah, const __half* __restrict__ Bh,
    const float* __restrict__ bias, const float* __restrict__ res,
    float* __restrict__ outf, __half* __restrict__ outh,
    int M, int N, int K)
{
    extern __shared__ __align__(16) char smem[];
    const uint32_t base = smem_u32(smem);
    const int tid = threadIdx.x;
    const int wid = tid >> 5, lane = tid & 31;
    const int wm = wid >> 2, wn = wid & 3;
    const int m0 = blockIdx.y * 128, n0 = blockIdx.x * 256;

    const __half* gA = Ah + (size_t)m0 * K;
    const __half* gB = Bh + (size_t)n0 * K;

    auto stage = [&](int k0, int buf) {
        const uint32_t sb = base + buf * GSTAGE;
        #pragma unroll
        for (int i = 0; i < 4; i++) {
            int idx = tid + i * 256;
            int r = idx >> 3, s = idx & 7;
            cp16(sb + (r * GRS + s * 8) * 2, gA + (size_t)r * K + k0 + s * 8);
        }
        #pragma unroll
        for (int i = 0; i < 8; i++) {
            int idx = tid + i * 256;
            int r = idx >> 3, s = idx & 7;
            cp16(sb + ATB + (r * GRS + s * 8) * 2, gB + (size_t)r * K + k0 + s * 8);
        }
        asm volatile("cp.async.commit_group;");
    };

    const int laRowA = ((lane >> 3) & 1) * 8 + (lane & 7);
    const int laColA = (lane >> 4) * 8;
    const int laRowB = ((lane >> 4) << 3) + (lane & 7);
    const int laColB = ((lane >> 3) & 1) * 8;

    float c[4][8][4];
    #pragma unroll
    for (int i = 0; i < 4; i++)
        #pragma unroll
        for (int j = 0; j < 8; j++)
            #pragma unroll
            for (int q = 0; q < 4; q++) c[i][j][q] = 0.f;

    const int nch = K >> 6;
    stage(0, 0);
    stage(64, 1);

    for (int ch = 0; ch < nch; ch++) {
        if (ch + 1 < nch) asm volatile("cp.async.wait_group 1;");
        else              asm volatile("cp.async.wait_group 0;");
        __syncthreads();
        if (ch + 2 < nch) stage((ch + 2) << 6, (ch + 2) % 3);

        const uint32_t sb = base + (ch % 3) * GSTAGE;
        const uint32_t sA = sb, sB = sb + ATB;

        #pragma unroll
        for (int ks = 0; ks < 64; ks += 16) {
            uint32_t a[4][4];
            #pragma unroll
            for (int mf = 0; mf < 4; mf++) {
                uint32_t off = ((wm * 64 + mf * 16 + laRowA) * GRS + ks + laColA) * 2;
                ldsm4(sA + off, a[mf][0], a[mf][1], a[mf][2], a[mf][3]);
            }
            uint32_t bh[8][2];
            #pragma unroll
            for (int np = 0; np < 4; np++) {
                uint32_t off = ((wn * 64 + np * 16 + laRowB) * GRS + ks + laColB) * 2;
                ldsm4(sB + off, bh[2*np][0], bh[2*np][1], bh[2*np+1][0], bh[2*np+1][1]);
            }
            #pragma unroll
            for (int mf = 0; mf < 4; mf++)
                #pragma unroll
                for (int nf = 0; nf < 8; nf++)
                    mma_f16(c[mf][nf], a[mf], bh[nf][0], bh[nf][1]);
        }
    }

    #pragma unroll
    for (int mf = 0; mf < 4; mf++) {
        const int rbase = m0 + wm * 64 + mf * 16 + (lane >> 2);
        #pragma unroll
        for (int nf = 0; nf < 8; nf++) {
            const int gn = n0 + wn * 64 + nf * 8 + (lane & 3) * 2;
            const float2 b2 = *(const float2*)(bias + gn);
            #pragma unroll
            for (int half_ = 0; half_ < 2; half_++) {
                const int gm = rbase + half_ * 8;
                float v0 = c[mf][nf][half_ * 2 + 0] + b2.x;
                float v1 = c[mf][nf][half_ * 2 + 1] + b2.y;
                if (GELU) { v0 = gelu_tanh(v0); v1 = gelu_tanh(v1); }
                if (OMODE == 0) {
                    if (res) {
                        const float2 r2 = *(const float2*)(res + (size_t)gm * N + gn);
                        v0 += r2.x; v1 += r2.y;
                    }
                    *(float2*)(outf + (size_t)gm * N + gn) = make_float2(v0, v1);
                } else {
                    *(uint32_t*)(outh + (size_t)gm * N + gn) =
                        pack2(__float2half(v0), __float2half(v1));
                }
            }
        }
    }
}

// ---------------------------------------------------------------------------
// Flash attention, fp16 single-pass. BQ=128 (8 warps), BK=64, D=64.
// ---------------------------------------------------------------------------
#define FRS 72
#define QTB (128 * FRS * 2)
#define KVT (64 * FRS * 2)
#define KVSTAGE (2 * KVT)
#define FLASH_SMEM (QTB + 2 * KVSTAGE)

template<bool CAUSAL>
__global__ __launch_bounds__(256, 1) void flash_mma(
    const __half* __restrict__ Qh,
    const __half* __restrict__ Kh, const __half* __restrict__ Vh,
    __half* __restrict__ Ohi,
    int Tq, int Tkv, int qS, int kS, float scale)
{
    extern __shared__ __align__(16) char smem[];
    const uint32_t base = smem_u32(smem);
    const uint32_t sQ = base;

    const int tid = threadIdx.x;
    const int wid = tid >> 5, lane = tid & 31;
    const int bh = blockIdx.y;
    const int b = bh >> 4, h = bh & 15;
    const int qt = blockIdx.x;

    const __half* Qb  = Qh + (size_t)(b * Tq + qt * 128) * qS + h * 64;
    const __half* Khb = Kh + (size_t)(b * Tkv) * kS + h * 64;
    const __half* Vhb = Vh + (size_t)(b * Tkv) * kS + h * 64;

    auto stage_kv = [&](int kt, int buf) {
        const uint32_t sb = base + QTB + buf * KVSTAGE;
        #pragma unroll
        for (int i = 0; i < 2; i++) {
            int idx = tid + i * 256;
            int r = idx >> 3, s = idx & 7;
            size_t go = (size_t)(kt * 64 + r) * kS + s * 8;
            uint32_t off = (r * FRS + s * 8) * 2;
            cp16(sb + 0 * KVT + off, Khb + go);
            cp16(sb + 1 * KVT + off, Vhb + go);
        }
        asm volatile("cp.async.commit_group;");
    };

    #pragma unroll
    for (int i = 0; i < 4; i++) {
        int idx = tid + i * 256;
        int r = idx >> 3, s = idx & 7;
        cp16(sQ + (r * FRS + s * 8) * 2, Qb + (size_t)r * qS + s * 8);
    }
    stage_kv(0, 0);

    const int laRowA = ((lane >> 3) & 1) * 8 + (lane & 7);
    const int laColA = (lane >> 4) * 8;
    const int laRowB = ((lane >> 4) << 3) + (lane & 7);
    const int laColB = ((lane >> 3) & 1) * 8;

    float o[8][4];
    #pragma unroll
    for (int i = 0; i < 8; i++)
        #pragma unroll
        for (int j = 0; j < 4; j++) o[i][j] = 0.f;
    float mr0 = -1e30f, mr1 = -1e30f, lr0 = 0.f, lr1 = 0.f;

    const int nkt = CAUSAL ? (2 * qt + 2) : (Tkv >> 6);

    for (int kt = 0; kt < nkt; kt++) {
        if (kt + 1 < nkt) {
            stage_kv(kt + 1, (kt + 1) & 1);
            asm volatile("cp.async.wait_group 1;");
        } else {
            asm volatile("cp.async.wait_group 0;");
        }
        __syncthreads();

        const uint32_t sb = base + QTB + (kt & 1) * KVSTAGE;
        const uint32_t sK = sb, sV = sb + KVT;

        float s[8][4];
        #pragma unroll
        for (int i = 0; i < 8; i++)
            #pragma unroll
            for (int j = 0; j < 4; j++) s[i][j] = 0.f;

        #pragma unroll
        for (int ks = 0; ks < 4; ks++) {
            uint32_t q[4];
            uint32_t qoff = ((wid * 16 + laRowA) * FRS + ks * 16 + laColA) * 2;
            ldsm4(sQ + qoff, q[0], q[1], q[2], q[3]);
            #pragma unroll
            for (int np = 0; np < 4; np++) {
                uint32_t koff = ((np * 16 + laRowB) * FRS + ks * 16 + laColB) * 2;
                uint32_t k0, k1, k2, k3;
                ldsm4(sK + koff, k0, k1, k2, k3);
                mma_f16(s[2*np],   q, k0, k1);
                mma_f16(s[2*np+1], q, k2, k3);
            }
        }
        #pragma unroll
        for (int i = 0; i < 8; i++)
            #pragma unroll
            for (int j = 0; j < 4; j++) s[i][j] *= scale;

        if (CAUSAL && kt >= 2 * qt) {
            const int row0 = qt * 128 + wid * 16 + (lane >> 2);
            #pragma unroll
            for (int nf = 0; nf < 8; nf++) {
                const int col = kt * 64 + nf * 8 + (lane & 3) * 2;
                if (col     > row0)     s[nf][0] = -1e30f;
                if (col + 1 > row0)     s[nf][1] = -1e30f;
                if (col     > row0 + 8) s[nf][2] = -1e30f;
                if (col + 1 > row0 + 8) s[nf][3] = -1e30f;
            }
        }

        float t0 = -1e30f, t1 = -1e30f;
        #pragma unroll
        for (int nf = 0; nf < 8; nf++) {
            t0 = fmaxf(t0, fmaxf(s[nf][0], s[nf][1]));
            t1 = fmaxf(t1, fmaxf(s[nf][2], s[nf][3]));
        }
        t0 = fmaxf(t0, __shfl_xor_sync(0xffffffffu, t0, 1));
        t0 = fmaxf(t0, __shfl_xor_sync(0xffffffffu, t0, 2));
        t1 = fmaxf(t1, __shfl_xor_sync(0xffffffffu, t1, 1));
        t1 = fmaxf(t1, __shfl_xor_sync(0xffffffffu, t1, 2));
        const float nm0 = fmaxf(mr0, t0), nm1 = fmaxf(mr1, t1);
        const float f0 = __expf(mr0 - nm0), f1 = __expf(mr1 - nm1);
        mr0 = nm0; mr1 = nm1;

        float rs0 = 0.f, rs1 = 0.f;
        #pragma unroll
        for (int nf = 0; nf < 8; nf++) {
            s[nf][0] = __expf(s[nf][0] - nm0);
            s[nf][1] = __expf(s[nf][1] - nm0);
            s[nf][2] = __expf(s[nf][2] - nm1);
            s[nf][3] = __expf(s[nf][3] - nm1);
            rs0 += s[nf][0] + s[nf][1];
            rs1 += s[nf][2] + s[nf][3];
        }
        rs0 += __shfl_xor_sync(0xffffffffu, rs0, 1);
        rs0 += __shfl_xor_sync(0xffffffffu, rs0, 2);
        rs1 += __shfl_xor_sync(0xffffffffu, rs1, 1);
        rs1 += __shfl_xor_sync(0xffffffffu, rs1, 2);
        lr0 = lr0 * f0 + rs0;
        lr1 = lr1 * f1 + rs1;
        #pragma unroll
        for (int nf = 0; nf < 8; nf++) {
            o[nf][0] *= f0; o[nf][1] *= f0;
            o[nf][2] *= f1; o[nf][3] *= f1;
        }

        uint32_t ph[4][4];
        #pragma unroll
        for (int j = 0; j < 4; j++) {
            ph[j][0] = pack2(__float2half(s[2*j][0]),   __float2half(s[2*j][1]));
            ph[j][1] = pack2(__float2half(s[2*j][2]),   __float2half(s[2*j][3]));
            ph[j][2] = pack2(__float2half(s[2*j+1][0]), __float2half(s[2*j+1][1]));
            ph[j][3] = pack2(__float2half(s[2*j+1][2]), __float2half(s[2*j+1][3]));
        }

        #pragma unroll
        for (int j = 0; j < 4; j++) {
            #pragma unroll
            for (int np = 0; np < 4; np++) {
                uint32_t voff = ((j * 16 + laRowA) * FRS + np * 16 + laColA) * 2;
                uint32_t v0, v1, v2, v3;
                ldsm4t(sV + voff, v0, v1, v2, v3);
                mma_f16(o[2*np],   ph[j], v0, v1);
                mma_f16(o[2*np+1], ph[j], v2, v3);
            }
        }
        __syncthreads();
    }

    const float inv0 = 1.0f / lr0, inv1 = 1.0f / lr1;
    const int row0 = qt * 128 + wid * 16 + (lane >> 2);
    #pragma unroll
    for (int nf = 0; nf < 8; nf++) {
        const int col = h * 64 + nf * 8 + (lane & 3) * 2;
        {
            size_t off = (size_t)(b * Tq + row0) * CC + col;
            *(uint32_t*)(Ohi + off) =
                pack2(__float2half(o[nf][0] * inv0), __float2half(o[nf][1] * inv0));
        }
        {
            size_t off = (size_t)(b * Tq + row0 + 8) * CC + col;
            *(uint32_t*)(Ohi + off) =
                pack2(__float2half(o[nf][2] * inv1), __float2half(o[nf][3] * inv1));
        }
    }
}

// ---------------------------------------------------------------------------
// Launch sequence
// ---------------------------------------------------------------------------
extern "C" void kernel_launch(void* const* d_in, const int* in_sizes, int n_in,
                              void* d_out, int out_size)
{
    (void)in_sizes; (void)n_in; (void)out_size;
    const float* x      = (const float*)d_in[0];
    const float* ximg   = (const float*)d_in[1];
    const float* ln1_g  = (const float*)d_in[2];
    const float* ln1_b  = (const float*)d_in[3];
    const float* ln2_g  = (const float*)d_in[4];
    const float* ln2_b  = (const float*)d_in[5];
    const float* W_attn = (const float*)d_in[6];
    const float* b_attn = (const float*)d_in[7];
    const float* W_aproj= (const float*)d_in[8];
    const float* b_aproj= (const float*)d_in[9];
    const float* Wq     = (const float*)d_in[10];
    const float* bq     = (const float*)d_in[11];
    const float* Wk     = (const float*)d_in[12];
    const float* bk     = (const float*)d_in[13];
    const float* Wv     = (const float*)d_in[14];
    const float* bv     = (const float*)d_in[15];
    const float* Wcproj = (const float*)d_in[16];
    const float* bcproj = (const float*)d_in[17];
    const float* W_fc   = (const float*)d_in[18];
    const float* b_fc   = (const float*)d_in[19];
    const float* W_mproj= (const float*)d_in[20];
    const float* b_mproj= (const float*)d_in[21];
    float* out = (float*)d_out;

    __half *wt, *qkv, *q, *kv, *a, *ff, *xi;
    float* bkv;
    cudaGetSymbolAddress((void**)&wt,  g_wt);
    cudaGetSymbolAddress((void**)&qkv, g_qkv);
    cudaGetSymbolAddress((void**)&q,   g_q);
    cudaGetSymbolAddress((void**)&kv,  g_kv);
    cudaGetSymbolAddress((void**)&a,   g_a);
    cudaGetSymbolAddress((void**)&ff,  g_ff);
    cudaGetSymbolAddress((void**)&xi,  g_xi);
    cudaGetSymbolAddress((void**)&bkv, g_bkv);

    cudaFuncSetAttribute(mma_gemm<0,false>, cudaFuncAttributeMaxDynamicSharedMemorySize, GEMM_SMEM);
    cudaFuncSetAttribute(mma_gemm<1,false>, cudaFuncAttributeMaxDynamicSharedMemorySize, GEMM_SMEM);
    cudaFuncSetAttribute(mma_gemm<1,true>,  cudaFuncAttributeMaxDynamicSharedMemorySize, GEMM_SMEM);
    cudaFuncSetAttribute(flash_mma<true>,  cudaFuncAttributeMaxDynamicSharedMemorySize, FLASH_SMEM);
    cudaFuncSetAttribute(flash_mma<false>, cudaFuncAttributeMaxDynamicSharedMemorySize, FLASH_SMEM);

    const float scale = 0.125f;

    // ---- prep ----
    tofp16_kernel<<<(MIMG*CC + 255)/256, 256>>>(ximg, xi, MIMG*CC);
    concat_bias_kernel<<<(2*CC + 255)/256, 256>>>(bk, bv, bkv);

    Prep8 pp;
    pp.d[0] = { W_attn,  OFF_ATTN,  CC, 3*CC, (3*CC/32)*(CC/32) };
    pp.d[1] = { W_aproj, OFF_APROJ, CC, CC,   (CC/32)*(CC/32)   };
    pp.d[2] = { Wq,      OFF_Q,     CC, CC,   (CC/32)*(CC/32)   };
    pp.d[3] = { Wk,      OFF_K,     CC, CC,   (CC/32)*(CC/32)   };
    pp.d[4] = { Wv,      OFF_V,     CC, CC,   (CC/32)*(CC/32)   };
    pp.d[5] = { Wcproj,  OFF_CPROJ, CC, CC,   (CC/32)*(CC/32)   };
    pp.d[6] = { W_fc,    OFF_FC,    CC, FFD,  (FFD/32)*(CC/32)  };
    pp.d[7] = { W_mproj, OFF_MPROJ, FFD, CC,  (CC/32)*(FFD/32)  };
    prep_weights_kernel<<<3072 + 5*1024 + 2*4096, 256>>>(pp, wt);

    // ---- causal self-attention ----
    ln_h_kernel<<<MM, 256>>>(x, ln1_g, ln1_b, a);
    mma_gemm<1,false><<<dim3(3*CC/256, MM/128), 256, GEMM_SMEM>>>(
        a, wt+OFF_ATTN, b_attn, nullptr, nullptr, qkv, MM, 3*CC, CC);
    flash_mma<true><<<dim3(8, 128), 256, FLASH_SMEM>>>(
        qkv, qkv + CC, qkv + 2*CC, a, 1024, 1024, 3*CC, 3*CC, scale);
    mma_gemm<0,false><<<dim3(CC/256, MM/128), 256, GEMM_SMEM>>>(
        a, wt+OFF_APROJ, b_aproj, x, out, nullptr, MM, CC, CC);

    // ---- cross-attention ----
    ln_h_kernel<<<MM, 256>>>(out, ln1_g, ln1_b, a);
    mma_gemm<1,false><<<dim3(CC/256, MM/128), 256, GEMM_SMEM>>>(
        a, wt+OFF_Q, bq, nullptr, nullptr, q, MM, CC, CC);
    mma_gemm<1,false><<<dim3(2*CC/256, MIMG/128), 256, GEMM_SMEM>>>(
        xi, wt+OFF_K, bkv, nullptr, nullptr, kv, MIMG, 2*CC, CC);
    flash_mma<false><<<dim3(8, 128), 256, FLASH_SMEM>>>(
        q, kv, kv + CC, a, 1024, 256, CC, 2*CC, scale);
    mma_gemm<0,false><<<dim3(CC/256, MM/128), 256, GEMM_SMEM>>>(
        a, wt+OFF_CPROJ, bcproj, out, out, nullptr, MM, CC, CC);

    // ---- MLP ----
    ln_h_kernel<<<MM, 256>>>(out, ln2_g, ln2_b, a);
    mma_gemm<1,true><<<dim3(FFD/256, MM/128), 256, GEMM_SMEM>>>(
        a, wt+OFF_FC, b_fc, nullptr, nullptr, ff, MM, FFD, CC);
    mma_gemm<0,false><<<dim3(CC/256, MM/128), 256, GEMM_SMEM>>>(
        ff, wt+OFF_MPROJ, b_mproj, out, out, nullptr, MM, CC, FFD);
}

// round 15
// speedup vs baseline: 1.0465x; 1.0009x over previous
#include <cuda_runtime.h>
#include <cuda_fp16.h>
#include <cstdint>
#include <math.h>

#define CC    1024
#define MM    8192
#define MIMG  2048
#define FFD   4096

// ---------------------------------------------------------------------------
// helpers
// ---------------------------------------------------------------------------
__device__ __forceinline__ uint32_t smem_u32(const void* p) {
    uint32_t a;
    asm("{ .reg .u64 t; cvta.to.shared.u64 t, %1; cvt.u32.u64 %0, t; }" : "=r"(a) : "l"(p));
    return a;
}
__device__ __forceinline__ void ldsm4(uint32_t a, uint32_t& r0, uint32_t& r1,
                                      uint32_t& r2, uint32_t& r3) {
    asm volatile("ldmatrix.sync.aligned.m8n8.x4.shared.b16 {%0,%1,%2,%3}, [%4];"
                 : "=r"(r0), "=r"(r1), "=r"(r2), "=r"(r3) : "r"(a));
}
__device__ __forceinline__ void ldsm4t(uint32_t a, uint32_t& r0, uint32_t& r1,
                                       uint32_t& r2, uint32_t& r3) {
    asm volatile("ldmatrix.sync.aligned.m8n8.x4.trans.shared.b16 {%0,%1,%2,%3}, [%4];"
                 : "=r"(r0), "=r"(r1), "=r"(r2), "=r"(r3) : "r"(a));
}
__device__ __forceinline__ void mma_f16(float* c, const uint32_t* a, uint32_t b0, uint32_t b1) {
    asm volatile("mma.sync.aligned.m16n8k16.row.col.f32.f16.f16.f32 "
                 "{%0,%1,%2,%3}, {%4,%5,%6,%7}, {%8,%9}, {%0,%1,%2,%3};"
                 : "+f"(c[0]), "+f"(c[1]), "+f"(c[2]), "+f"(c[3])
                 : "r"(a[0]), "r"(a[1]), "r"(a[2]), "r"(a[3]), "r"(b0), "r"(b1));
}
__device__ __forceinline__ void cp16(uint32_t dst, const void* src) {
    asm volatile("cp.async.cg.shared.global [%0], [%1], 16;" :: "r"(dst), "l"(src));
}
__device__ __forceinline__ uint32_t pack2(__half a, __half b) {
    __half2 t = __halves2half2(a, b);
    return *reinterpret_cast<uint32_t*>(&t);
}
__device__ __forceinline__ float htanh(float x) {
    float r;
    asm("tanh.approx.f32 %0, %1;" : "=f"(r) : "f"(x));
    return r;
}
__device__ __forceinline__ float gelu_tanh(float x) {
    float u = 0.7978845608028654f * (x + 0.044715f * x * x * x);
    return 0.5f * x * (1.0f + htanh(u));
}

// ---------------------------------------------------------------------------
// Scratch
// ---------------------------------------------------------------------------
__device__ __half g_wt[16777216];          // transposed fp16 weights [N,K]
__device__ __half g_qkv[MM * 3 * CC];
__device__ __half g_q[MM * CC];
__device__ __half g_kv[MIMG * 2 * CC];
__device__ __half g_a[MM * CC];
__device__ __half g_ff[MM * FFD];
__device__ __half g_xi[MIMG * CC];
__device__ float g_bkv[2 * CC];

#define OFF_ATTN  0u
#define OFF_APROJ 3145728u
#define OFF_Q     4194304u
#define OFF_K     5242880u
#define OFF_V     6291456u
#define OFF_CPROJ 7340032u
#define OFF_FC    8388608u
#define OFF_MPROJ 12582912u

// ---------------------------------------------------------------------------
// batched transpose+cast: all 8 weights in ONE launch.
// ---------------------------------------------------------------------------
struct PrepDesc {
    const float* W;
    uint32_t dstOff;
    int K, N;
    int tiles;
};
struct Prep8 { PrepDesc d[8]; };

__global__ __launch_bounds__(256) void prep_weights_kernel(Prep8 p, __half* dstBase)
{
    __shared__ float t[32][33];
    int bid = blockIdx.x;
    int di = 0;
    #pragma unroll
    for (int i = 0; i < 7; i++)
        if (bid >= p.d[di].tiles) { bid -= p.d[di].tiles; di++; }
    const PrepDesc& d = p.d[di];
    const int ntiles_n = d.N >> 5;
    const int n0 = (bid % ntiles_n) * 32;
    const int k0 = (bid / ntiles_n) * 32;
    {
        const int tx = threadIdx.x & 31, ty = threadIdx.x >> 5;
        #pragma unroll
        for (int i = 0; i < 4; i++) {
            int kk = ty + i * 8;
            t[kk][tx] = d.W[(size_t)(k0 + kk) * d.N + n0 + tx];
        }
    }
    __syncthreads();
    __half* dst = dstBase + d.dstOff;
    const int kp = threadIdx.x & 15;
    const int nyb = threadIdx.x >> 4;
    #pragma unroll
    for (int i = 0; i < 2; i++) {
        int nn = nyb + i * 16;
        uint32_t v = pack2(__float2half(t[2*kp][nn]), __float2half(t[2*kp+1][nn]));
        *(uint32_t*)(dst + (size_t)(n0 + nn) * d.K + k0 + 2*kp) = v;
    }
}

__global__ void tofp16_kernel(const float* __restrict__ x,
                              __half* __restrict__ o, int n)
{
    int i = blockIdx.x * blockDim.x + threadIdx.x;
    if (i < n) o[i] = __float2half(x[i]);
}

__global__ void concat_bias_kernel(const float* __restrict__ a,
                                   const float* __restrict__ b,
                                   float* __restrict__ o)
{
    int i = blockIdx.x * blockDim.x + threadIdx.x;
    if (i < CC) o[i] = a[i];
    else if (i < 2 * CC) o[i] = b[i - CC];
}

// ---------------------------------------------------------------------------
// single-pass pair reduction + LayerNorm (fp16 output)
// ---------------------------------------------------------------------------
__device__ __forceinline__ float2 block_sum2(float a, float b) {
    __shared__ float2 red[8];
    int lane = threadIdx.x & 31;
    int w    = threadIdx.x >> 5;
    #pragma unroll
    for (int o = 16; o; o >>= 1) {
        a += __shfl_xor_sync(0xffffffffu, a, o);
        b += __shfl_xor_sync(0xffffffffu, b, o);
    }
    if (lane == 0) red[w] = make_float2(a, b);
    __syncthreads();
    if (w == 0) {
        float2 v = (lane < 8) ? red[lane] : make_float2(0.f, 0.f);
        #pragma unroll
        for (int o = 4; o; o >>= 1) {
            v.x += __shfl_xor_sync(0xffffffffu, v.x, o);
            v.y += __shfl_xor_sync(0xffffffffu, v.y, o);
        }
        if (lane == 0) red[0] = v;
    }
    __syncthreads();
    return red[0];
}

__global__ __launch_bounds__(256) void ln_h_kernel(
    const float* __restrict__ in, const float* __restrict__ g,
    const float* __restrict__ b, __half* __restrict__ out)
{
    const int row = blockIdx.x;
    const float4 v = ((const float4*)(in + (size_t)row * CC))[threadIdx.x];
    float s = v.x + v.y + v.z + v.w;
    float q = v.x*v.x + v.y*v.y + v.z*v.z + v.w*v.w;
    float2 r = block_sum2(s, q);
    const float mean = r.x * (1.0f / CC);
    const float var  = r.y * (1.0f / CC) - mean * mean;
    const float rstd = rsqrtf(var + 1e-5f);
    const float4 gg = ((const float4*)g)[threadIdx.x];
    const float4 bb = ((const float4*)b)[threadIdx.x];
    __half h0 = __float2half((v.x - mean) * rstd * gg.x + bb.x);
    __half h1 = __float2half((v.y - mean) * rstd * gg.y + bb.y);
    __half h2 = __float2half((v.z - mean) * rstd * gg.z + bb.z);
    __half h3 = __float2half((v.w - mean) * rstd * gg.w + bb.w);
    size_t off = (size_t)row * CC + threadIdx.x * 4;
    *(uint2*)(out + off) = make_uint2(pack2(h0,h1), pack2(h2,h3));
}

// ---------------------------------------------------------------------------
// HMMA fp16 single-pass GEMM body (device function).
// Block tile 128x256x64; 8 warps 2(M)x4(N); 3-stage cp.async.
// OMODE: 0 = fp32 out (+res), 1 = fp16 out
// ---------------------------------------------------------------------------
#define GRS 72
#define ATB (128 * GRS * 2)
#define BTB (256 * GRS * 2)
#define GSTAGE (ATB + BTB)
#define GEMM_SMEM (3 * GSTAGE)

template<int OMODE, bool GELU>
__device__ __forceinline__ void gemm_body(
    char* smem,
    const __half* __restrict__ Ah, const __half* __restrict__ Bh,
    const float* __restrict__ bias, const float* __restrict__ res,
    float* __restrict__ outf, __half* __restrict__ outh,
    int M, int N, int K, int m0, int n0)
{
    const uint32_t base = smem_u32(smem);
    const int tid = threadIdx.x;
    const int wid = tid >> 5, lane = tid & 31;
    const int wm = wid >> 2, wn = wid & 3;

    const __half* gA = Ah + (size_t)m0 * K;
    const __half* gB = Bh + (size_t)n0 * K;

    auto stage = [&](int k0, int buf) {
        const uint32_t sb = base + buf * GSTAGE;
        #pragma unroll
        for (int i = 0; i < 4; i++) {
            int idx = tid + i * 256;
            int r = idx >> 3, s = idx & 7;
            cp16(sb + (r * GRS + s * 8) * 2, gA + (size_t)r * K + k0 + s * 8);
        }
        #pragma unroll
        for (int i = 0; i < 8; i++) {
            int idx = tid + i * 256;
            int r = idx >> 3, s = idx & 7;
            cp16(sb + ATB + (r * GRS + s * 8) * 2, gB + (size_t)r * K + k0 + s * 8);
        }
        asm volatile("cp.async.commit_group;");
    };

    const int laRowA = ((lane >> 3) & 1) * 8 + (lane & 7);
    const int laColA = (lane >> 4) * 8;
    const int laRowB = ((lane >> 4) << 3) + (lane & 7);
    const int laColB = ((lane >> 3) & 1) * 8;

    float c[4][8][4];
    #pragma unroll
    for (int i = 0; i < 4; i++)
        #pragma unroll
        for (int j = 0; j < 8; j++)
            #pragma unroll
            for (int q = 0; q < 4; q++) c[i][j][q] = 0.f;

    const int nch = K >> 6;
    stage(0, 0);
    stage(64, 1);

    for (int ch = 0; ch < nch; ch++) {
        if (ch + 1 < nch) asm volatile("cp.async.wait_group 1;");
        else              asm volatile("cp.async.wait_group 0;");
        __syncthreads();
        if (ch + 2 < nch) stage((ch + 2) << 6, (ch + 2) % 3);

        const uint32_t sb = base + (ch % 3) * GSTAGE;
        const uint32_t sA = sb, sB = sb + ATB;

        #pragma unroll
        for (int ks = 0; ks < 64; ks += 16) {
            uint32_t a[4][4];
            #pragma unroll
            for (int mf = 0; mf < 4; mf++) {
                uint32_t off = ((wm * 64 + mf * 16 + laRowA) * GRS + ks + laColA) * 2;
                ldsm4(sA + off, a[mf][0], a[mf][1], a[mf][2], a[mf][3]);
            }
            uint32_t bh[8][2];
            #pragma unroll
            for (int np = 0; np < 4; np++) {
                uint32_t off = ((wn * 64 + np * 16 + laRowB) * GRS + ks + laColB) * 2;
                ldsm4(sB + off, bh[2*np][0], bh[2*np][1], bh[2*np+1][0], bh[2*np+1][1]);
            }
            #pragma unroll
            for (int mf = 0; mf < 4; mf++)
                #pragma unroll
                for (int nf = 0; nf < 8; nf++)
                    mma_f16(c[mf][nf], a[mf], bh[nf][0], bh[nf][1]);
        }
    }

    #pragma unroll
    for (int mf = 0; mf < 4; mf++) {
        const int rbase = m0 + wm * 64 + mf * 16 + (lane >> 2);
        #pragma unroll
        for (int nf = 0; nf < 8; nf++) {
            const int gn = n0 + wn * 64 + nf * 8 + (lane & 3) * 2;
            const float2 b2 = *(const float2*)(bias + gn);
            #pragma unroll
            for (int half_ = 0; half_ < 2; half_++) {
                const int gm = rbase + half_ * 8;
                float v0 = c[mf][nf][half_ * 2 + 0] + b2.x;
                float v1 = c[mf][nf][half_ * 2 + 1] + b2.y;
                if (GELU) { v0 = gelu_tanh(v0); v1 = gelu_tanh(v1); }
                if (OMODE == 0) {
                    if (res) {
                        const float2 r2 = *(const float2*)(res + (size_t)gm * N + gn);
                        v0 += r2.x; v1 += r2.y;
                    }
                    *(float2*)(outf + (size_t)gm * N + gn) = make_float2(v0, v1);
                } else {
                    *(uint32_t*)(outh + (size_t)gm * N + gn) =
                        pack2(__float2half(v0), __float2half(v1));
                }
            }
        }
    }
}

template<int OMODE, bool GELU>
__global__ __launch_bounds__(256, 1) void mma_gemm(
    const __half* __restrict__ Ah, const __half* __restrict__ Bh,
    const float* __restrict__ bias, const float* __restrict__ res,
    float* __restrict__ outf, __half* __restrict__ outh,
    int M, int N, int K)
{
    extern __shared__ __align__(16) char smem[];
    gemm_body<OMODE, GELU>(smem, Ah, Bh, bias, res, outf, outh, M, N, K,
                           blockIdx.y * 128, blockIdx.x * 256);
}

// Two independent fp16-out GEMMs fused into one launch (flattened 1D grid).
struct GemmDesc {
    const __half* A; const __half* B; const float* bias; __half* out;
    int M, N, K, gx, tiles;
};
__global__ __launch_bounds__(256, 1) void mma_gemm_pair(GemmDesc d0, GemmDesc d1)
{
    extern __shared__ __align__(16) char smem[];
    int bid = blockIdx.x;
    if (bid < d0.tiles) {
        gemm_body<1, false>(smem, d0.A, d0.B, d0.bias, nullptr, nullptr, d0.out,
                            d0.M, d0.N, d0.K, (bid / d0.gx) * 128, (bid % d0.gx) * 256);
    } else {
        bid -= d0.tiles;
        gemm_body<1, false>(smem, d1.A, d1.B, d1.bias, nullptr, nullptr, d1.out,
                            d1.M, d1.N, d1.K, (bid / d1.gx) * 128, (bid % d1.gx) * 256);
    }
}

// ---------------------------------------------------------------------------
// Flash attention, fp16 single-pass. BQ=128 (8 warps), BK=64, D=64.
// ---------------------------------------------------------------------------
#define FRS 72
#define QTB (128 * FRS * 2)
#define KVT (64 * FRS * 2)
#define KVSTAGE (2 * KVT)
#define FLASH_SMEM (QTB + 2 * KVSTAGE)

template<bool CAUSAL>
__global__ __launch_bounds__(256, 1) void flash_mma(
    const __half* __restrict__ Qh,
    const __half* __restrict__ Kh, const __half* __restrict__ Vh,
    __half* __restrict__ Ohi,
    int Tq, int Tkv, int qS, int kS, float scale)
{
    extern __shared__ __align__(16) char smem[];
    const uint32_t base = smem_u32(smem);
    const uint32_t sQ = base;

    const int tid = threadIdx.x;
    const int wid = tid >> 5, lane = tid & 31;
    const int bh = blockIdx.y;
    const int b = bh >> 4, h = bh & 15;
    const int qt = blockIdx.x;

    const __half* Qb  = Qh + (size_t)(b * Tq + qt * 128) * qS + h * 64;
    const __half* Khb = Kh + (size_t)(b * Tkv) * kS + h * 64;
    const __half* Vhb = Vh + (size_t)(b * Tkv) * kS + h * 64;

    auto stage_kv = [&](int kt, int buf) {
        const uint32_t sb = base + QTB + buf * KVSTAGE;
        #pragma unroll
        for (int i = 0; i < 2; i++) {
            int idx = tid + i * 256;
            int r = idx >> 3, s = idx & 7;
            size_t go = (size_t)(kt * 64 + r) * kS + s * 8;
            uint32_t off = (r * FRS + s * 8) * 2;
            cp16(sb + 0 * KVT + off, Khb + go);
            cp16(sb + 1 * KVT + off, Vhb + go);
        }
        asm volatile("cp.async.commit_group;");
    };

    #pragma unroll
    for (int i = 0; i < 4; i++) {
        int idx = tid + i * 256;
        int r = idx >> 3, s = idx & 7;
        cp16(sQ + (r * FRS + s * 8) * 2, Qb + (size_t)r * qS + s * 8);
    }
    stage_kv(0, 0);

    const int laRowA = ((lane >> 3) & 1) * 8 + (lane & 7);
    const int laColA = (lane >> 4) * 8;
    const int laRowB = ((lane >> 4) << 3) + (lane & 7);
    const int laColB = ((lane >> 3) & 1) * 8;

    float o[8][4];
    #pragma unroll
    for (int i = 0; i < 8; i++)
        #pragma unroll
        for (int j = 0; j < 4; j++) o[i][j] = 0.f;
    float mr0 = -1e30f, mr1 = -1e30f, lr0 = 0.f, lr1 = 0.f;

    const int nkt = CAUSAL ? (2 * qt + 2) : (Tkv >> 6);

    for (int kt = 0; kt < nkt; kt++) {
        if (kt + 1 < nkt) {
            stage_kv(kt + 1, (kt + 1) & 1);
            asm volatile("cp.async.wait_group 1;");
        } else {
            asm volatile("cp.async.wait_group 0;");
        }
        __syncthreads();

        const uint32_t sb = base + QTB + (kt & 1) * KVSTAGE;
        const uint32_t sK = sb, sV = sb + KVT;

        float s[8][4];
        #pragma unroll
        for (int i = 0; i < 8; i++)
            #pragma unroll
            for (int j = 0; j < 4; j++) s[i][j] = 0.f;

        #pragma unroll
        for (int ks = 0; ks < 4; ks++) {
            uint32_t q[4];
            uint32_t qoff = ((wid * 16 + laRowA) * FRS + ks * 16 + laColA) * 2;
            ldsm4(sQ + qoff, q[0], q[1], q[2], q[3]);
            #pragma unroll
            for (int np = 0; np < 4; np++) {
                uint32_t koff = ((np * 16 + laRowB) * FRS + ks * 16 + laColB) * 2;
                uint32_t k0, k1, k2, k3;
                ldsm4(sK + koff, k0, k1, k2, k3);
                mma_f16(s[2*np],   q, k0, k1);
                mma_f16(s[2*np+1], q, k2, k3);
            }
        }
        #pragma unroll
        for (int i = 0; i < 8; i++)
            #pragma unroll
            for (int j = 0; j < 4; j++) s[i][j] *= scale;

        if (CAUSAL && kt >= 2 * qt) {
            const int row0 = qt * 128 + wid * 16 + (lane >> 2);
            #pragma unroll
            for (int nf = 0; nf < 8; nf++) {
                const int col = kt * 64 + nf * 8 + (lane & 3) * 2;
                if (col     > row0)     s[nf][0] = -1e30f;
                if (col + 1 > row0)     s[nf][1] = -1e30f;
                if (col     > row0 + 8) s[nf][2] = -1e30f;
                if (col + 1 > row0 + 8) s[nf][3] = -1e30f;
            }
        }

        float t0 = -1e30f, t1 = -1e30f;
        #pragma unroll
        for (int nf = 0; nf < 8; nf++) {
            t0 = fmaxf(t0, fmaxf(s[nf][0], s[nf][1]));
            t1 = fmaxf(t1, fmaxf(s[nf][2], s[nf][3]));
        }
        t0 = fmaxf(t0, __shfl_xor_sync(0xffffffffu, t0, 1));
        t0 = fmaxf(t0, __shfl_xor_sync(0xffffffffu, t0, 2));
        t1 = fmaxf(t1, __shfl_xor_sync(0xffffffffu, t1, 1));
        t1 = fmaxf(t1, __shfl_xor_sync(0xffffffffu, t1, 2));
        const float nm0 = fmaxf(mr0, t0), nm1 = fmaxf(mr1, t1);
        const float f0 = __expf(mr0 - nm0), f1 = __expf(mr1 - nm1);
        mr0 = nm0; mr1 = nm1;

        float rs0 = 0.f, rs1 = 0.f;
        #pragma unroll
        for (int nf = 0; nf < 8; nf++) {
            s[nf][0] = __expf(s[nf][0] - nm0);
            s[nf][1] = __expf(s[nf][1] - nm0);
            s[nf][2] = __expf(s[nf][2] - nm1);
            s[nf][3] = __expf(s[nf][3] - nm1);
            rs0 += s[nf][0] + s[nf][1];
            rs1 += s[nf][2] + s[nf][3];
        }
        rs0 += __shfl_xor_sync(0xffffffffu, rs0, 1);
        rs0 += __shfl_xor_sync(0xffffffffu, rs0, 2);
        rs1 += __shfl_xor_sync(0xffffffffu, rs1, 1);
        rs1 += __shfl_xor_sync(0xffffffffu, rs1, 2);
        lr0 = lr0 * f0 + rs0;
        lr1 = lr1 * f1 + rs1;
        #pragma unroll
        for (int nf = 0; nf < 8; nf++) {
            o[nf][0] *= f0; o[nf][1] *= f0;
            o[nf][2] *= f1; o[nf][3] *= f1;
        }

        uint32_t ph[4][4];
        #pragma unroll
        for (int j = 0; j < 4; j++) {
            ph[j][0] = pack2(__float2half(s[2*j][0]),   __float2half(s[2*j][1]));
            ph[j][1] = pack2(__float2half(s[2*j][2]),   __float2half(s[2*j][3]));
            ph[j][2] = pack2(__float2half(s[2*j+1][0]), __float2half(s[2*j+1][1]));
            ph[j][3] = pack2(__float2half(s[2*j+1][2]), __float2half(s[2*j+1][3]));
        }

        #pragma unroll
        for (int j = 0; j < 4; j++) {
            #pragma unroll
            for (int np = 0; np < 4; np++) {
                uint32_t voff = ((j * 16 + laRowA) * FRS + np * 16 + laColA) * 2;
                uint32_t v0, v1, v2, v3;
                ldsm4t(sV + voff, v0, v1, v2, v3);
                mma_f16(o[2*np],   ph[j], v0, v1);
                mma_f16(o[2*np+1], ph[j], v2, v3);
            }
        }
        __syncthreads();
    }

    const float inv0 = 1.0f / lr0, inv1 = 1.0f / lr1;
    const int row0 = qt * 128 + wid * 16 + (lane >> 2);
    #pragma unroll
    for (int nf = 0; nf < 8; nf++) {
        const int col = h * 64 + nf * 8 + (lane & 3) * 2;
        {
            size_t off = (size_t)(b * Tq + row0) * CC + col;
            *(uint32_t*)(Ohi + off) =
                pack2(__float2half(o[nf][0] * inv0), __float2half(o[nf][1] * inv0));
        }
        {
            size_t off = (size_t)(b * Tq + row0 + 8) * CC + col;
            *(uint32_t*)(Ohi + off) =
                pack2(__float2half(o[nf][2] * inv1), __float2half(o[nf][3] * inv1));
        }
    }
}

// ---------------------------------------------------------------------------
// Launch sequence
// ---------------------------------------------------------------------------
extern "C" void kernel_launch(void* const* d_in, const int* in_sizes, int n_in,
                              void* d_out, int out_size)
{
    (void)in_sizes; (void)n_in; (void)out_size;
    const float* x      = (const float*)d_in[0];
    const float* ximg   = (const float*)d_in[1];
    const float* ln1_g  = (const float*)d_in[2];
    const float* ln1_b  = (const float*)d_in[3];
    const float* ln2_g  = (const float*)d_in[4];
    const float* ln2_b  = (const float*)d_in[5];
    const float* W_attn = (const float*)d_in[6];
    const float* b_attn = (const float*)d_in[7];
    const float* W_aproj= (const float*)d_in[8];
    const float* b_aproj= (const float*)d_in[9];
    const float* Wq     = (const float*)d_in[10];
    const float* bq     = (const float*)d_in[11];
    const float* Wk     = (const float*)d_in[12];
    const float* bk     = (const float*)d_in[13];
    const float* Wv     = (const float*)d_in[14];
    const float* bv     = (const float*)d_in[15];
    const float* Wcproj = (const float*)d_in[16];
    const float* bcproj = (const float*)d_in[17];
    const float* W_fc   = (const float*)d_in[18];
    const float* b_fc   = (const float*)d_in[19];
    const float* W_mproj= (const float*)d_in[20];
    const float* b_mproj= (const float*)d_in[21];
    float* out = (float*)d_out;

    __half *wt, *qkv, *q, *kv, *a, *ff, *xi;
    float* bkv;
    cudaGetSymbolAddress((void**)&wt,  g_wt);
    cudaGetSymbolAddress((void**)&qkv, g_qkv);
    cudaGetSymbolAddress((void**)&q,   g_q);
    cudaGetSymbolAddress((void**)&kv,  g_kv);
    cudaGetSymbolAddress((void**)&a,   g_a);
    cudaGetSymbolAddress((void**)&ff,  g_ff);
    cudaGetSymbolAddress((void**)&xi,  g_xi);
    cudaGetSymbolAddress((void**)&bkv, g_bkv);

    cudaFuncSetAttribute(mma_gemm<0,false>, cudaFuncAttributeMaxDynamicSharedMemorySize, GEMM_SMEM);
    cudaFuncSetAttribute(mma_gemm<1,false>, cudaFuncAttributeMaxDynamicSharedMemorySize, GEMM_SMEM);
    cudaFuncSetAttribute(mma_gemm<1,true>,  cudaFuncAttributeMaxDynamicSharedMemorySize, GEMM_SMEM);
    cudaFuncSetAttribute(mma_gemm_pair,     cudaFuncAttributeMaxDynamicSharedMemorySize, GEMM_SMEM);
    cudaFuncSetAttribute(flash_mma<true>,  cudaFuncAttributeMaxDynamicSharedMemorySize, FLASH_SMEM);
    cudaFuncSetAttribute(flash_mma<false>, cudaFuncAttributeMaxDynamicSharedMemorySize, FLASH_SMEM);

    const float scale = 0.125f;

    // ---- prep (ordered so the qkv GEMM is my-launch #3 → ncu capture) ----
    ln_h_kernel<<<MM, 256>>>(x, ln1_g, ln1_b, a);                              // 0
    Prep8 pp;
    pp.d[0] = { W_attn,  OFF_ATTN,  CC, 3*CC, (3*CC/32)*(CC/32) };
    pp.d[1] = { W_aproj, OFF_APROJ, CC, CC,   (CC/32)*(CC/32)   };
    pp.d[2] = { Wq,      OFF_Q,     CC, CC,   (CC/32)*(CC/32)   };
    pp.d[3] = { Wk,      OFF_K,     CC, CC,   (CC/32)*(CC/32)   };
    pp.d[4] = { Wv,      OFF_V,     CC, CC,   (CC/32)*(CC/32)   };
    pp.d[5] = { Wcproj,  OFF_CPROJ, CC, CC,   (CC/32)*(CC/32)   };
    pp.d[6] = { W_fc,    OFF_FC,    CC, FFD,  (FFD/32)*(CC/32)  };
    pp.d[7] = { W_mproj, OFF_MPROJ, FFD, CC,  (CC/32)*(FFD/32)  };
    prep_weights_kernel<<<3072 + 5*1024 + 2*4096, 256>>>(pp, wt);              // 1
    tofp16_kernel<<<(MIMG*CC + 255)/256, 256>>>(ximg, xi, MIMG*CC);            // 2

    // ---- causal self-attention ----
    mma_gemm<1,false><<<dim3(3*CC/256, MM/128), 256, GEMM_SMEM>>>(             // 3 (ncu)
        a, wt+OFF_ATTN, b_attn, nullptr, nullptr, qkv, MM, 3*CC, CC);
    concat_bias_kernel<<<(2*CC + 255)/256, 256>>>(bk, bv, bkv);                // 4
    flash_mma<true><<<dim3(8, 128), 256, FLASH_SMEM>>>(
        qkv, qkv + CC, qkv + 2*CC, a, 1024, 1024, 3*CC, 3*CC, scale);
    mma_gemm<0,false><<<dim3(CC/256, MM/128), 256, GEMM_SMEM>>>(
        a, wt+OFF_APROJ, b_aproj, x, out, nullptr, MM, CC, CC);

    // ---- cross-attention ----
    ln_h_kernel<<<MM, 256>>>(out, ln1_g, ln1_b, a);
    {
        GemmDesc d0 = { a,  wt+OFF_Q, bq,  q,  MM,   CC,   CC, CC/256,   (CC/256)*(MM/128)    };
        GemmDesc d1 = { xi, wt+OFF_K, bkv, kv, MIMG, 2*CC, CC, 2*CC/256, (2*CC/256)*(MIMG/128) };
        mma_gemm_pair<<<d0.tiles + d1.tiles, 256, GEMM_SMEM>>>(d0, d1);
    }
    flash_mma<false><<<dim3(8, 128), 256, FLASH_SMEM>>>(
        q, kv, kv + CC, a, 1024, 256, CC, 2*CC, scale);
    mma_gemm<0,false><<<dim3(CC/256, MM/128), 256, GEMM_SMEM>>>(
        a, wt+OFF_CPROJ, bcproj, out, out, nullptr, MM, CC, CC);

    // ---- MLP ----
    ln_h_kernel<<<MM, 256>>>(out, ln2_g, ln2_b, a);
    mma_gemm<1,true><<<dim3(FFD/256, MM/128), 256, GEMM_SMEM>>>(
        a, wt+OFF_FC, b_fc, nullptr, nullptr, ff, MM, FFD, CC);
    mma_gemm<0,false><<<dim3(CC/256, MM/128), 256, GEMM_SMEM>>>(
        ff, wt+OFF_MPROJ, b_mproj, out, out, nullptr, MM, CC, FFD);
}

// round 16
// speedup vs baseline: 1.1059x; 1.0567x over previous
#include <cuda_runtime.h>
#include <cuda_fp16.h>
#include <cstdint>
#include <math.h>

#define CC    1024
#define MM    8192
#define MIMG  2048
#define FFD   4096

// ---------------------------------------------------------------------------
// helpers
// ---------------------------------------------------------------------------
__device__ __forceinline__ uint32_t smem_u32(const void* p) {
    uint32_t a;
    asm("{ .reg .u64 t; cvta.to.shared.u64 t, %1; cvt.u32.u64 %0, t; }" : "=r"(a) : "l"(p));
    return a;
}
__device__ __forceinline__ void ldsm4(uint32_t a, uint32_t& r0, uint32_t& r1,
                                      uint32_t& r2, uint32_t& r3) {
    asm volatile("ldmatrix.sync.aligned.m8n8.x4.shared.b16 {%0,%1,%2,%3}, [%4];"
                 : "=r"(r0), "=r"(r1), "=r"(r2), "=r"(r3) : "r"(a));
}
__device__ __forceinline__ void ldsm4t(uint32_t a, uint32_t& r0, uint32_t& r1,
                                       uint32_t& r2, uint32_t& r3) {
    asm volatile("ldmatrix.sync.aligned.m8n8.x4.trans.shared.b16 {%0,%1,%2,%3}, [%4];"
                 : "=r"(r0), "=r"(r1), "=r"(r2), "=r"(r3) : "r"(a));
}
__device__ __forceinline__ void mma_f16(float* c, const uint32_t* a, uint32_t b0, uint32_t b1) {
    asm volatile("mma.sync.aligned.m16n8k16.row.col.f32.f16.f16.f32 "
                 "{%0,%1,%2,%3}, {%4,%5,%6,%7}, {%8,%9}, {%0,%1,%2,%3};"
                 : "+f"(c[0]), "+f"(c[1]), "+f"(c[2]), "+f"(c[3])
                 : "r"(a[0]), "r"(a[1]), "r"(a[2]), "r"(a[3]), "r"(b0), "r"(b1));
}
__device__ __forceinline__ void cp16(uint32_t dst, const void* src) {
    asm volatile("cp.async.cg.shared.global [%0], [%1], 16;" :: "r"(dst), "l"(src));
}
__device__ __forceinline__ uint32_t pack2(__half a, __half b) {
    __half2 t = __halves2half2(a, b);
    return *reinterpret_cast<uint32_t*>(&t);
}
__device__ __forceinline__ float htanh(float x) {
    float r;
    asm("tanh.approx.f32 %0, %1;" : "=f"(r) : "f"(x));
    return r;
}
__device__ __forceinline__ float gelu_tanh(float x) {
    float u = 0.7978845608028654f * (x + 0.044715f * x * x * x);
    return 0.5f * x * (1.0f + htanh(u));
}

// ---------------------------------------------------------------------------
// Scratch
// ---------------------------------------------------------------------------
__device__ __half g_wt[16777216];          // transposed fp16 weights [N,K]
__device__ __half g_qkv[MM * 3 * CC];
__device__ __half g_q[MM * CC];
__device__ __half g_kv[MIMG * 2 * CC];
__device__ __half g_a[MM * CC];
__device__ __half g_ff[MM * FFD];
__device__ __half g_xi[MIMG * CC];
__device__ float g_bkv[2 * CC];

#define OFF_ATTN  0u
#define OFF_APROJ 3145728u
#define OFF_Q     4194304u
#define OFF_K     5242880u
#define OFF_V     6291456u
#define OFF_CPROJ 7340032u
#define OFF_FC    8388608u
#define OFF_MPROJ 12582912u

// ---------------------------------------------------------------------------
// batched transpose+cast: all 8 weights in ONE launch.
// ---------------------------------------------------------------------------
struct PrepDesc {
    const float* W;
    uint32_t dstOff;
    int K, N;
    int tiles;
};
struct Prep8 { PrepDesc d[8]; };

__global__ __launch_bounds__(256) void prep_weights_kernel(Prep8 p, __half* dstBase)
{
    __shared__ float t[32][33];
    int bid = blockIdx.x;
    int di = 0;
    #pragma unroll
    for (int i = 0; i < 7; i++)
        if (bid >= p.d[di].tiles) { bid -= p.d[di].tiles; di++; }
    const PrepDesc& d = p.d[di];
    const int ntiles_n = d.N >> 5;
    const int n0 = (bid % ntiles_n) * 32;
    const int k0 = (bid / ntiles_n) * 32;
    {
        const int tx = threadIdx.x & 31, ty = threadIdx.x >> 5;
        #pragma unroll
        for (int i = 0; i < 4; i++) {
            int kk = ty + i * 8;
            t[kk][tx] = d.W[(size_t)(k0 + kk) * d.N + n0 + tx];
        }
    }
    __syncthreads();
    __half* dst = dstBase + d.dstOff;
    const int kp = threadIdx.x & 15;
    const int nyb = threadIdx.x >> 4;
    #pragma unroll
    for (int i = 0; i < 2; i++) {
        int nn = nyb + i * 16;
        uint32_t v = pack2(__float2half(t[2*kp][nn]), __float2half(t[2*kp+1][nn]));
        *(uint32_t*)(dst + (size_t)(n0 + nn) * d.K + k0 + 2*kp) = v;
    }
}

__global__ void tofp16_kernel(const float* __restrict__ x,
                              __half* __restrict__ o, int n)
{
    int i = blockIdx.x * blockDim.x + threadIdx.x;
    if (i < n) o[i] = __float2half(x[i]);
}

__global__ void concat_bias_kernel(const float* __restrict__ a,
                                   const float* __restrict__ b,
                                   float* __restrict__ o)
{
    int i = blockIdx.x * blockDim.x + threadIdx.x;
    if (i < CC) o[i] = a[i];
    else if (i < 2 * CC) o[i] = b[i - CC];
}

// ---------------------------------------------------------------------------
// single-pass pair reduction + LayerNorm (fp16 output)
// ---------------------------------------------------------------------------
__device__ __forceinline__ float2 block_sum2(float a, float b) {
    __shared__ float2 red[8];
    int lane = threadIdx.x & 31;
    int w    = threadIdx.x >> 5;
    #pragma unroll
    for (int o = 16; o; o >>= 1) {
        a += __shfl_xor_sync(0xffffffffu, a, o);
        b += __shfl_xor_sync(0xffffffffu, b, o);
    }
    if (lane == 0) red[w] = make_float2(a, b);
    __syncthreads();
    if (w == 0) {
        float2 v = (lane < 8) ? red[lane] : make_float2(0.f, 0.f);
        #pragma unroll
        for (int o = 4; o; o >>= 1) {
            v.x += __shfl_xor_sync(0xffffffffu, v.x, o);
            v.y += __shfl_xor_sync(0xffffffffu, v.y, o);
        }
        if (lane == 0) red[0] = v;
    }
    __syncthreads();
    return red[0];
}

__global__ __launch_bounds__(256) void ln_h_kernel(
    const float* __restrict__ in, const float* __restrict__ g,
    const float* __restrict__ b, __half* __restrict__ out)
{
    const int row = blockIdx.x;
    const float4 v = ((const float4*)(in + (size_t)row * CC))[threadIdx.x];
    float s = v.x + v.y + v.z + v.w;
    float q = v.x*v.x + v.y*v.y + v.z*v.z + v.w*v.w;
    float2 r = block_sum2(s, q);
    const float mean = r.x * (1.0f / CC);
    const float var  = r.y * (1.0f / CC) - mean * mean;
    const float rstd = rsqrtf(var + 1e-5f);
    const float4 gg = ((const float4*)g)[threadIdx.x];
    const float4 bb = ((const float4*)b)[threadIdx.x];
    __half h0 = __float2half((v.x - mean) * rstd * gg.x + bb.x);
    __half h1 = __float2half((v.y - mean) * rstd * gg.y + bb.y);
    __half h2 = __float2half((v.z - mean) * rstd * gg.z + bb.z);
    __half h3 = __float2half((v.w - mean) * rstd * gg.w + bb.w);
    size_t off = (size_t)row * CC + threadIdx.x * 4;
    *(uint2*)(out + off) = make_uint2(pack2(h0,h1), pack2(h2,h3));
}

// ---------------------------------------------------------------------------
// HMMA fp16 single-pass GEMM body.
// Block tile 128x128x64; 8 warps 2(M)x4(N) -> warp tile 64x32; 3-stage cp.async.
// 2 CTAs/SM (smem 110.6KB total, regs capped at 128).
// OMODE: 0 = fp32 out (+res), 1 = fp16 out
// ---------------------------------------------------------------------------
#define GRS 72
#define ATB (128 * GRS * 2)              // 18432
#define BTB (128 * GRS * 2)              // 18432
#define GSTAGE (ATB + BTB)               // 36864
#define GEMM_SMEM (3 * GSTAGE)           // 110592

template<int OMODE, bool GELU>
__device__ __forceinline__ void gemm_body(
    char* smem,
    const __half* __restrict__ Ah, const __half* __restrict__ Bh,
    const float* __restrict__ bias, const float* __restrict__ res,
    float* __restrict__ outf, __half* __restrict__ outh,
    int M, int N, int K, int m0, int n0)
{
    const uint32_t base = smem_u32(smem);
    const int tid = threadIdx.x;
    const int wid = tid >> 5, lane = tid & 31;
    const int wm = wid >> 2, wn = wid & 3;   // 2(M) x 4(N)

    const __half* gA = Ah + (size_t)m0 * K;
    const __half* gB = Bh + (size_t)n0 * K;

    auto stage = [&](int k0, int buf) {
        const uint32_t sb = base + buf * GSTAGE;
        #pragma unroll
        for (int i = 0; i < 4; i++) {
            int idx = tid + i * 256;
            int r = idx >> 3, s = idx & 7;
            cp16(sb + (r * GRS + s * 8) * 2, gA + (size_t)r * K + k0 + s * 8);
        }
        #pragma unroll
        for (int i = 0; i < 4; i++) {
            int idx = tid + i * 256;
            int r = idx >> 3, s = idx & 7;
            cp16(sb + ATB + (r * GRS + s * 8) * 2, gB + (size_t)r * K + k0 + s * 8);
        }
        asm volatile("cp.async.commit_group;");
    };

    const int laRowA = ((lane >> 3) & 1) * 8 + (lane & 7);
    const int laColA = (lane >> 4) * 8;
    const int laRowB = ((lane >> 4) << 3) + (lane & 7);
    const int laColB = ((lane >> 3) & 1) * 8;

    float c[4][4][4];
    #pragma unroll
    for (int i = 0; i < 4; i++)
        #pragma unroll
        for (int j = 0; j < 4; j++)
            #pragma unroll
            for (int q = 0; q < 4; q++) c[i][j][q] = 0.f;

    const int nch = K >> 6;
    stage(0, 0);
    stage(64, 1);

    for (int ch = 0; ch < nch; ch++) {
        if (ch + 1 < nch) asm volatile("cp.async.wait_group 1;");
        else              asm volatile("cp.async.wait_group 0;");
        __syncthreads();
        if (ch + 2 < nch) stage((ch + 2) << 6, (ch + 2) % 3);

        const uint32_t sb = base + (ch % 3) * GSTAGE;
        const uint32_t sA = sb, sB = sb + ATB;

        #pragma unroll
        for (int ks = 0; ks < 64; ks += 16) {
            uint32_t a[4][4];
            #pragma unroll
            for (int mf = 0; mf < 4; mf++) {
                uint32_t off = ((wm * 64 + mf * 16 + laRowA) * GRS + ks + laColA) * 2;
                ldsm4(sA + off, a[mf][0], a[mf][1], a[mf][2], a[mf][3]);
            }
            uint32_t bh[4][2];
            #pragma unroll
            for (int np = 0; np < 2; np++) {
                uint32_t off = ((wn * 32 + np * 16 + laRowB) * GRS + ks + laColB) * 2;
                ldsm4(sB + off, bh[2*np][0], bh[2*np][1], bh[2*np+1][0], bh[2*np+1][1]);
            }
            #pragma unroll
            for (int mf = 0; mf < 4; mf++)
                #pragma unroll
                for (int nf = 0; nf < 4; nf++)
                    mma_f16(c[mf][nf], a[mf], bh[nf][0], bh[nf][1]);
        }
    }

    #pragma unroll
    for (int mf = 0; mf < 4; mf++) {
        const int rbase = m0 + wm * 64 + mf * 16 + (lane >> 2);
        #pragma unroll
        for (int nf = 0; nf < 4; nf++) {
            const int gn = n0 + wn * 32 + nf * 8 + (lane & 3) * 2;
            const float2 b2 = *(const float2*)(bias + gn);
            #pragma unroll
            for (int half_ = 0; half_ < 2; half_++) {
                const int gm = rbase + half_ * 8;
                float v0 = c[mf][nf][half_ * 2 + 0] + b2.x;
                float v1 = c[mf][nf][half_ * 2 + 1] + b2.y;
                if (GELU) { v0 = gelu_tanh(v0); v1 = gelu_tanh(v1); }
                if (OMODE == 0) {
                    if (res) {
                        const float2 r2 = *(const float2*)(res + (size_t)gm * N + gn);
                        v0 += r2.x; v1 += r2.y;
                    }
                    *(float2*)(outf + (size_t)gm * N + gn) = make_float2(v0, v1);
                } else {
                    *(uint32_t*)(outh + (size_t)gm * N + gn) =
                        pack2(__float2half(v0), __float2half(v1));
                }
            }
        }
    }
}

template<int OMODE, bool GELU>
__global__ __launch_bounds__(256, 2) void mma_gemm(
    const __half* __restrict__ Ah, const __half* __restrict__ Bh,
    const float* __restrict__ bias, const float* __restrict__ res,
    float* __restrict__ outf, __half* __restrict__ outh,
    int M, int N, int K)
{
    extern __shared__ __align__(16) char smem[];
    gemm_body<OMODE, GELU>(smem, Ah, Bh, bias, res, outf, outh, M, N, K,
                           blockIdx.y * 128, blockIdx.x * 128);
}

// Two independent fp16-out GEMMs fused into one launch (flattened 1D grid).
struct GemmDesc {
    const __half* A; const __half* B; const float* bias; __half* out;
    int M, N, K, gx, tiles;
};
__global__ __launch_bounds__(256, 2) void mma_gemm_pair(GemmDesc d0, GemmDesc d1)
{
    extern __shared__ __align__(16) char smem[];
    int bid = blockIdx.x;
    if (bid < d0.tiles) {
        gemm_body<1, false>(smem, d0.A, d0.B, d0.bias, nullptr, nullptr, d0.out,
                            d0.M, d0.N, d0.K, (bid / d0.gx) * 128, (bid % d0.gx) * 128);
    } else {
        bid -= d0.tiles;
        gemm_body<1, false>(smem, d1.A, d1.B, d1.bias, nullptr, nullptr, d1.out,
                            d1.M, d1.N, d1.K, (bid / d1.gx) * 128, (bid % d1.gx) * 128);
    }
}

// ---------------------------------------------------------------------------
// Flash attention, fp16 single-pass. BQ=128 (8 warps), BK=64, D=64.
// ---------------------------------------------------------------------------
#define FRS 72
#define QTB (128 * FRS * 2)
#define KVT (64 * FRS * 2)
#define KVSTAGE (2 * KVT)
#define FLASH_SMEM (QTB + 2 * KVSTAGE)

template<bool CAUSAL>
__global__ __launch_bounds__(256, 1) void flash_mma(
    const __half* __restrict__ Qh,
    const __half* __restrict__ Kh, const __half* __restrict__ Vh,
    __half* __restrict__ Ohi,
    int Tq, int Tkv, int qS, int kS, float scale)
{
    extern __shared__ __align__(16) char smem[];
    const uint32_t base = smem_u32(smem);
    const uint32_t sQ = base;

    const int tid = threadIdx.x;
    const int wid = tid >> 5, lane = tid & 31;
    const int bh = blockIdx.y;
    const int b = bh >> 4, h = bh & 15;
    const int qt = blockIdx.x;

    const __half* Qb  = Qh + (size_t)(b * Tq + qt * 128) * qS + h * 64;
    const __half* Khb = Kh + (size_t)(b * Tkv) * kS + h * 64;
    const __half* Vhb = Vh + (size_t)(b * Tkv) * kS + h * 64;

    auto stage_kv = [&](int kt, int buf) {
        const uint32_t sb = base + QTB + buf * KVSTAGE;
        #pragma unroll
        for (int i = 0; i < 2; i++) {
            int idx = tid + i * 256;
            int r = idx >> 3, s = idx & 7;
            size_t go = (size_t)(kt * 64 + r) * kS + s * 8;
            uint32_t off = (r * FRS + s * 8) * 2;
            cp16(sb + 0 * KVT + off, Khb + go);
            cp16(sb + 1 * KVT + off, Vhb + go);
        }
        asm volatile("cp.async.commit_group;");
    };

    #pragma unroll
    for (int i = 0; i < 4; i++) {
        int idx = tid + i * 256;
        int r = idx >> 3, s = idx & 7;
        cp16(sQ + (r * FRS + s * 8) * 2, Qb + (size_t)r * qS + s * 8);
    }
    stage_kv(0, 0);

    const int laRowA = ((lane >> 3) & 1) * 8 + (lane & 7);
    const int laColA = (lane >> 4) * 8;
    const int laRowB = ((lane >> 4) << 3) + (lane & 7);
    const int laColB = ((lane >> 3) & 1) * 8;

    float o[8][4];
    #pragma unroll
    for (int i = 0; i < 8; i++)
        #pragma unroll
        for (int j = 0; j < 4; j++) o[i][j] = 0.f;
    float mr0 = -1e30f, mr1 = -1e30f, lr0 = 0.f, lr1 = 0.f;

    const int nkt = CAUSAL ? (2 * qt + 2) : (Tkv >> 6);

    for (int kt = 0; kt < nkt; kt++) {
        if (kt + 1 < nkt) {
            stage_kv(kt + 1, (kt + 1) & 1);
            asm volatile("cp.async.wait_group 1;");
        } else {
            asm volatile("cp.async.wait_group 0;");
        }
        __syncthreads();

        const uint32_t sb = base + QTB + (kt & 1) * KVSTAGE;
        const uint32_t sK = sb, sV = sb + KVT;

        float s[8][4];
        #pragma unroll
        for (int i = 0; i < 8; i++)
            #pragma unroll
            for (int j = 0; j < 4; j++) s[i][j] = 0.f;

        #pragma unroll
        for (int ks = 0; ks < 4; ks++) {
            uint32_t q[4];
            uint32_t qoff = ((wid * 16 + laRowA) * FRS + ks * 16 + laColA) * 2;
            ldsm4(sQ + qoff, q[0], q[1], q[2], q[3]);
            #pragma unroll
            for (int np = 0; np < 4; np++) {
                uint32_t koff = ((np * 16 + laRowB) * FRS + ks * 16 + laColB) * 2;
                uint32_t k0, k1, k2, k3;
                ldsm4(sK + koff, k0, k1, k2, k3);
                mma_f16(s[2*np],   q, k0, k1);
                mma_f16(s[2*np+1], q, k2, k3);
            }
        }
        #pragma unroll
        for (int i = 0; i < 8; i++)
            #pragma unroll
            for (int j = 0; j < 4; j++) s[i][j] *= scale;

        if (CAUSAL && kt >= 2 * qt) {
            const int row0 = qt * 128 + wid * 16 + (lane >> 2);
            #pragma unroll
            for (int nf = 0; nf < 8; nf++) {
                const int col = kt * 64 + nf * 8 + (lane & 3) * 2;
                if (col     > row0)     s[nf][0] = -1e30f;
                if (col + 1 > row0)     s[nf][1] = -1e30f;
                if (col     > row0 + 8) s[nf][2] = -1e30f;
                if (col + 1 > row0 + 8) s[nf][3] = -1e30f;
            }
        }

        float t0 = -1e30f, t1 = -1e30f;
        #pragma unroll
        for (int nf = 0; nf < 8; nf++) {
            t0 = fmaxf(t0, fmaxf(s[nf][0], s[nf][1]));
            t1 = fmaxf(t1, fmaxf(s[nf][2], s[nf][3]));
        }
        t0 = fmaxf(t0, __shfl_xor_sync(0xffffffffu, t0, 1));
        t0 = fmaxf(t0, __shfl_xor_sync(0xffffffffu, t0, 2));
        t1 = fmaxf(t1, __shfl_xor_sync(0xffffffffu, t1, 1));
        t1 = fmaxf(t1, __shfl_xor_sync(0xffffffffu, t1, 2));
        const float nm0 = fmaxf(mr0, t0), nm1 = fmaxf(mr1, t1);
        const float f0 = __expf(mr0 - nm0), f1 = __expf(mr1 - nm1);
        mr0 = nm0; mr1 = nm1;

        float rs0 = 0.f, rs1 = 0.f;
        #pragma unroll
        for (int nf = 0; nf < 8; nf++) {
            s[nf][0] = __expf(s[nf][0] - nm0);
            s[nf][1] = __expf(s[nf][1] - nm0);
            s[nf][2] = __expf(s[nf][2] - nm1);
            s[nf][3] = __expf(s[nf][3] - nm1);
            rs0 += s[nf][0] + s[nf][1];
            rs1 += s[nf][2] + s[nf][3];
        }
        rs0 += __shfl_xor_sync(0xffffffffu, rs0, 1);
        rs0 += __shfl_xor_sync(0xffffffffu, rs0, 2);
        rs1 += __shfl_xor_sync(0xffffffffu, rs1, 1);
        rs1 += __shfl_xor_sync(0xffffffffu, rs1, 2);
        lr0 = lr0 * f0 + rs0;
        lr1 = lr1 * f1 + rs1;
        #pragma unroll
        for (int nf = 0; nf < 8; nf++) {
            o[nf][0] *= f0; o[nf][1] *= f0;
            o[nf][2] *= f1; o[nf][3] *= f1;
        }

        uint32_t ph[4][4];
        #pragma unroll
        for (int j = 0; j < 4; j++) {
            ph[j][0] = pack2(__float2half(s[2*j][0]),   __float2half(s[2*j][1]));
            ph[j][1] = pack2(__float2half(s[2*j][2]),   __float2half(s[2*j][3]));
            ph[j][2] = pack2(__float2half(s[2*j+1][0]), __float2half(s[2*j+1][1]));
            ph[j][3] = pack2(__float2half(s[2*j+1][2]), __float2half(s[2*j+1][3]));
        }

        #pragma unroll
        for (int j = 0; j < 4; j++) {
            #pragma unroll
            for (int np = 0; np < 4; np++) {
                uint32_t voff = ((j * 16 + laRowA) * FRS + np * 16 + laColA) * 2;
                uint32_t v0, v1, v2, v3;
                ldsm4t(sV + voff, v0, v1, v2, v3);
                mma_f16(o[2*np],   ph[j], v0, v1);
                mma_f16(o[2*np+1], ph[j], v2, v3);
            }
        }
        __syncthreads();
    }

    const float inv0 = 1.0f / lr0, inv1 = 1.0f / lr1;
    const int row0 = qt * 128 + wid * 16 + (lane >> 2);
    #pragma unroll
    for (int nf = 0; nf < 8; nf++) {
        const int col = h * 64 + nf * 8 + (lane & 3) * 2;
        {
            size_t off = (size_t)(b * Tq + row0) * CC + col;
            *(uint32_t*)(Ohi + off) =
                pack2(__float2half(o[nf][0] * inv0), __float2half(o[nf][1] * inv0));
        }
        {
            size_t off = (size_t)(b * Tq + row0 + 8) * CC + col;
            *(uint32_t*)(Ohi + off) =
                pack2(__float2half(o[nf][2] * inv1), __float2half(o[nf][3] * inv1));
        }
    }
}

// ---------------------------------------------------------------------------
// Launch sequence
// ---------------------------------------------------------------------------
extern "C" void kernel_launch(void* const* d_in, const int* in_sizes, int n_in,
                              void* d_out, int out_size)
{
    (void)in_sizes; (void)n_in; (void)out_size;
    const float* x      = (const float*)d_in[0];
    const float* ximg   = (const float*)d_in[1];
    const float* ln1_g  = (const float*)d_in[2];
    const float* ln1_b  = (const float*)d_in[3];
    const float* ln2_g  = (const float*)d_in[4];
    const float* ln2_b  = (const float*)d_in[5];
    const float* W_attn = (const float*)d_in[6];
    const float* b_attn = (const float*)d_in[7];
    const float* W_aproj= (const float*)d_in[8];
    const float* b_aproj= (const float*)d_in[9];
    const float* Wq     = (const float*)d_in[10];
    const float* bq     = (const float*)d_in[11];
    const float* Wk     = (const float*)d_in[12];
    const float* bk     = (const float*)d_in[13];
    const float* Wv     = (const float*)d_in[14];
    const float* bv     = (const float*)d_in[15];
    const float* Wcproj = (const float*)d_in[16];
    const float* bcproj = (const float*)d_in[17];
    const float* W_fc   = (const float*)d_in[18];
    const float* b_fc   = (const float*)d_in[19];
    const float* W_mproj= (const float*)d_in[20];
    const float* b_mproj= (const float*)d_in[21];
    float* out = (float*)d_out;

    __half *wt, *qkv, *q, *kv, *a, *ff, *xi;
    float* bkv;
    cudaGetSymbolAddress((void**)&wt,  g_wt);
    cudaGetSymbolAddress((void**)&qkv, g_qkv);
    cudaGetSymbolAddress((void**)&q,   g_q);
    cudaGetSymbolAddress((void**)&kv,  g_kv);
    cudaGetSymbolAddress((void**)&a,   g_a);
    cudaGetSymbolAddress((void**)&ff,  g_ff);
    cudaGetSymbolAddress((void**)&xi,  g_xi);
    cudaGetSymbolAddress((void**)&bkv, g_bkv);

    cudaFuncSetAttribute(mma_gemm<0,false>, cudaFuncAttributeMaxDynamicSharedMemorySize, GEMM_SMEM);
    cudaFuncSetAttribute(mma_gemm<1,false>, cudaFuncAttributeMaxDynamicSharedMemorySize, GEMM_SMEM);
    cudaFuncSetAttribute(mma_gemm<1,true>,  cudaFuncAttributeMaxDynamicSharedMemorySize, GEMM_SMEM);
    cudaFuncSetAttribute(mma_gemm_pair,     cudaFuncAttributeMaxDynamicSharedMemorySize, GEMM_SMEM);
    cudaFuncSetAttribute(flash_mma<true>,  cudaFuncAttributeMaxDynamicSharedMemorySize, FLASH_SMEM);
    cudaFuncSetAttribute(flash_mma<false>, cudaFuncAttributeMaxDynamicSharedMemorySize, FLASH_SMEM);

    const float scale = 0.125f;

    // ---- prep (ordered so the qkv GEMM is my-launch #3 → ncu capture) ----
    ln_h_kernel<<<MM, 256>>>(x, ln1_g, ln1_b, a);                              // 0
    Prep8 pp;
    pp.d[0] = { W_attn,  OFF_ATTN,  CC, 3*CC, (3*CC/32)*(CC/32) };
    pp.d[1] = { W_aproj, OFF_APROJ, CC, CC,   (CC/32)*(CC/32)   };
    pp.d[2] = { Wq,      OFF_Q,     CC, CC,   (CC/32)*(CC/32)   };
    pp.d[3] = { Wk,      OFF_K,     CC, CC,   (CC/32)*(CC/32)   };
    pp.d[4] = { Wv,      OFF_V,     CC, CC,   (CC/32)*(CC/32)   };
    pp.d[5] = { Wcproj,  OFF_CPROJ, CC, CC,   (CC/32)*(CC/32)   };
    pp.d[6] = { W_fc,    OFF_FC,    CC, FFD,  (FFD/32)*(CC/32)  };
    pp.d[7] = { W_mproj, OFF_MPROJ, FFD, CC,  (CC/32)*(FFD/32)  };
    prep_weights_kernel<<<3072 + 5*1024 + 2*4096, 256>>>(pp, wt);              // 1
    tofp16_kernel<<<(MIMG*CC + 255)/256, 256>>>(ximg, xi, MIMG*CC);            // 2

    // ---- causal self-attention ----
    mma_gemm<1,false><<<dim3(3*CC/128, MM/128), 256, GEMM_SMEM>>>(             // 3 (ncu)
        a, wt+OFF_ATTN, b_attn, nullptr, nullptr, qkv, MM, 3*CC, CC);
    concat_bias_kernel<<<(2*CC + 255)/256, 256>>>(bk, bv, bkv);                // 4
    flash_mma<true><<<dim3(8, 128), 256, FLASH_SMEM>>>(
        qkv, qkv + CC, qkv + 2*CC, a, 1024, 1024, 3*CC, 3*CC, scale);
    mma_gemm<0,false><<<dim3(CC/128, MM/128), 256, GEMM_SMEM>>>(
        a, wt+OFF_APROJ, b_aproj, x, out, nullptr, MM, CC, CC);

    // ---- cross-attention ----
    ln_h_kernel<<<MM, 256>>>(out, ln1_g, ln1_b, a);
    {
        GemmDesc d0 = { a,  wt+OFF_Q, bq,  q,  MM,   CC,   CC, CC/128,   (CC/128)*(MM/128)    };
        GemmDesc d1 = { xi, wt+OFF_K, bkv, kv, MIMG, 2*CC, CC, 2*CC/128, (2*CC/128)*(MIMG/128) };
        mma_gemm_pair<<<d0.tiles + d1.tiles, 256, GEMM_SMEM>>>(d0, d1);
    }
    flash_mma<false><<<dim3(8, 128), 256, FLASH_SMEM>>>(
        q, kv, kv + CC, a, 1024, 256, CC, 2*CC, scale);
    mma_gemm<0,false><<<dim3(CC/128, MM/128), 256, GEMM_SMEM>>>(
        a, wt+OFF_CPROJ, bcproj, out, out, nullptr, MM, CC, CC);

    // ---- MLP ----
    ln_h_kernel<<<MM, 256>>>(out, ln2_g, ln2_b, a);
    mma_gemm<1,true><<<dim3(FFD/128, MM/128), 256, GEMM_SMEM>>>(
        a, wt+OFF_FC, b_fc, nullptr, nullptr, ff, MM, FFD, CC);
    mma_gemm<0,false><<<dim3(CC/128, MM/128), 256, GEMM_SMEM>>>(
        ff, wt+OFF_MPROJ, b_mproj, out, out, nullptr, MM, CC, FFD);
}

// round 17
// speedup vs baseline: 1.1085x; 1.0024x over previous
#include <cuda_runtime.h>
#include <cuda_fp16.h>
#include <cstdint>
#include <math.h>

#define CC    1024
#define MM    8192
#define MIMG  2048
#define FFD   4096

// ---------------------------------------------------------------------------
// helpers
// ---------------------------------------------------------------------------
__device__ __forceinline__ uint32_t smem_u32(const void* p) {
    uint32_t a;
    asm("{ .reg .u64 t; cvta.to.shared.u64 t, %1; cvt.u32.u64 %0, t; }" : "=r"(a) : "l"(p));
    return a;
}
__device__ __forceinline__ void ldsm4(uint32_t a, uint32_t& r0, uint32_t& r1,
                                      uint32_t& r2, uint32_t& r3) {
    asm volatile("ldmatrix.sync.aligned.m8n8.x4.shared.b16 {%0,%1,%2,%3}, [%4];"
                 : "=r"(r0), "=r"(r1), "=r"(r2), "=r"(r3) : "r"(a));
}
__device__ __forceinline__ void ldsm4t(uint32_t a, uint32_t& r0, uint32_t& r1,
                                       uint32_t& r2, uint32_t& r3) {
    asm volatile("ldmatrix.sync.aligned.m8n8.x4.trans.shared.b16 {%0,%1,%2,%3}, [%4];"
                 : "=r"(r0), "=r"(r1), "=r"(r2), "=r"(r3) : "r"(a));
}
__device__ __forceinline__ void mma_f16(float* c, const uint32_t* a, uint32_t b0, uint32_t b1) {
    asm volatile("mma.sync.aligned.m16n8k16.row.col.f32.f16.f16.f32 "
                 "{%0,%1,%2,%3}, {%4,%5,%6,%7}, {%8,%9}, {%0,%1,%2,%3};"
                 : "+f"(c[0]), "+f"(c[1]), "+f"(c[2]), "+f"(c[3])
                 : "r"(a[0]), "r"(a[1]), "r"(a[2]), "r"(a[3]), "r"(b0), "r"(b1));
}
__device__ __forceinline__ void cp16(uint32_t dst, const void* src) {
    asm volatile("cp.async.cg.shared.global [%0], [%1], 16;" :: "r"(dst), "l"(src));
}
__device__ __forceinline__ uint32_t pack2(__half a, __half b) {
    __half2 t = __halves2half2(a, b);
    return *reinterpret_cast<uint32_t*>(&t);
}
__device__ __forceinline__ float htanh(float x) {
    float r;
    asm("tanh.approx.f32 %0, %1;" : "=f"(r) : "f"(x));
    return r;
}
__device__ __forceinline__ float gelu_tanh(float x) {
    float u = 0.7978845608028654f * (x + 0.044715f * x * x * x);
    return 0.5f * x * (1.0f + htanh(u));
}

// ---------------------------------------------------------------------------
// Scratch
// ---------------------------------------------------------------------------
__device__ __half g_wt[16777216];          // transposed fp16 weights [N,K]
__device__ __half g_qkv[MM * 3 * CC];
__device__ __half g_q[MM * CC];
__device__ __half g_kv[MIMG * 2 * CC];
__device__ __half g_a[MM * CC];
__device__ __half g_ff[MM * FFD];
__device__ __half g_xi[MIMG * CC];
__device__ float g_bkv[2 * CC];

#define OFF_ATTN  0u
#define OFF_APROJ 3145728u
#define OFF_Q     4194304u
#define OFF_K     5242880u
#define OFF_V     6291456u
#define OFF_CPROJ 7340032u
#define OFF_FC    8388608u
#define OFF_MPROJ 12582912u

// ---------------------------------------------------------------------------
// batched transpose+cast: all 8 weights in ONE launch.
// ---------------------------------------------------------------------------
struct PrepDesc {
    const float* W;
    uint32_t dstOff;
    int K, N;
    int tiles;
};
struct Prep8 { PrepDesc d[8]; };

__global__ __launch_bounds__(256) void prep_weights_kernel(Prep8 p, __half* dstBase)
{
    __shared__ float t[32][33];
    int bid = blockIdx.x;
    int di = 0;
    #pragma unroll
    for (int i = 0; i < 7; i++)
        if (bid >= p.d[di].tiles) { bid -= p.d[di].tiles; di++; }
    const PrepDesc& d = p.d[di];
    const int ntiles_n = d.N >> 5;
    const int n0 = (bid % ntiles_n) * 32;
    const int k0 = (bid / ntiles_n) * 32;
    {
        const int tx = threadIdx.x & 31, ty = threadIdx.x >> 5;
        #pragma unroll
        for (int i = 0; i < 4; i++) {
            int kk = ty + i * 8;
            t[kk][tx] = d.W[(size_t)(k0 + kk) * d.N + n0 + tx];
        }
    }
    __syncthreads();
    __half* dst = dstBase + d.dstOff;
    const int kp = threadIdx.x & 15;
    const int nyb = threadIdx.x >> 4;
    #pragma unroll
    for (int i = 0; i < 2; i++) {
        int nn = nyb + i * 16;
        uint32_t v = pack2(__float2half(t[2*kp][nn]), __float2half(t[2*kp+1][nn]));
        *(uint32_t*)(dst + (size_t)(n0 + nn) * d.K + k0 + 2*kp) = v;
    }
}

__global__ void tofp16_kernel(const float* __restrict__ x,
                              __half* __restrict__ o, int n)
{
    int i = blockIdx.x * blockDim.x + threadIdx.x;
    if (i < n) o[i] = __float2half(x[i]);
}

__global__ void concat_bias_kernel(const float* __restrict__ a,
                                   const float* __restrict__ b,
                                   float* __restrict__ o)
{
    int i = blockIdx.x * blockDim.x + threadIdx.x;
    if (i < CC) o[i] = a[i];
    else if (i < 2 * CC) o[i] = b[i - CC];
}

// ---------------------------------------------------------------------------
// single-pass pair reduction + LayerNorm (fp16 output)
// ---------------------------------------------------------------------------
__device__ __forceinline__ float2 block_sum2(float a, float b) {
    __shared__ float2 red[8];
    int lane = threadIdx.x & 31;
    int w    = threadIdx.x >> 5;
    #pragma unroll
    for (int o = 16; o; o >>= 1) {
        a += __shfl_xor_sync(0xffffffffu, a, o);
        b += __shfl_xor_sync(0xffffffffu, b, o);
    }
    if (lane == 0) red[w] = make_float2(a, b);
    __syncthreads();
    if (w == 0) {
        float2 v = (lane < 8) ? red[lane] : make_float2(0.f, 0.f);
        #pragma unroll
        for (int o = 4; o; o >>= 1) {
            v.x += __shfl_xor_sync(0xffffffffu, v.x, o);
            v.y += __shfl_xor_sync(0xffffffffu, v.y, o);
        }
        if (lane == 0) red[0] = v;
    }
    __syncthreads();
    return red[0];
}

__global__ __launch_bounds__(256) void ln_h_kernel(
    const float* __restrict__ in, const float* __restrict__ g,
    const float* __restrict__ b, __half* __restrict__ out)
{
    const int row = blockIdx.x;
    const float4 v = ((const float4*)(in + (size_t)row * CC))[threadIdx.x];
    float s = v.x + v.y + v.z + v.w;
    float q = v.x*v.x + v.y*v.y + v.z*v.z + v.w*v.w;
    float2 r = block_sum2(s, q);
    const float mean = r.x * (1.0f / CC);
    const float var  = r.y * (1.0f / CC) - mean * mean;
    const float rstd = rsqrtf(var + 1e-5f);
    const float4 gg = ((const float4*)g)[threadIdx.x];
    const float4 bb = ((const float4*)b)[threadIdx.x];
    __half h0 = __float2half((v.x - mean) * rstd * gg.x + bb.x);
    __half h1 = __float2half((v.y - mean) * rstd * gg.y + bb.y);
    __half h2 = __float2half((v.z - mean) * rstd * gg.z + bb.z);
    __half h3 = __float2half((v.w - mean) * rstd * gg.w + bb.w);
    size_t off = (size_t)row * CC + threadIdx.x * 4;
    *(uint2*)(out + off) = make_uint2(pack2(h0,h1), pack2(h2,h3));
}

// ---------------------------------------------------------------------------
// HMMA fp16 single-pass GEMM body.
// Block tile 128x128x64; 8 warps 2(M)x4(N) -> warp tile 64x32; 3-stage cp.async;
// fragment double-buffering inside the ks loop. 2 CTAs/SM.
// OMODE: 0 = fp32 out (+res), 1 = fp16 out
// ---------------------------------------------------------------------------
#define GRS 72
#define ATB (128 * GRS * 2)              // 18432
#define BTB (128 * GRS * 2)              // 18432
#define GSTAGE (ATB + BTB)               // 36864
#define GEMM_SMEM (3 * GSTAGE)           // 110592

template<int OMODE, bool GELU>
__device__ __forceinline__ void gemm_body(
    char* smem,
    const __half* __restrict__ Ah, const __half* __restrict__ Bh,
    const float* __restrict__ bias, const float* __restrict__ res,
    float* __restrict__ outf, __half* __restrict__ outh,
    int M, int N, int K, int m0, int n0)
{
    const uint32_t base = smem_u32(smem);
    const int tid = threadIdx.x;
    const int wid = tid >> 5, lane = tid & 31;
    const int wm = wid >> 2, wn = wid & 3;   // 2(M) x 4(N)

    const __half* gA = Ah + (size_t)m0 * K;
    const __half* gB = Bh + (size_t)n0 * K;

    auto stage = [&](int k0, int buf) {
        const uint32_t sb = base + buf * GSTAGE;
        #pragma unroll
        for (int i = 0; i < 4; i++) {
            int idx = tid + i * 256;
            int r = idx >> 3, s = idx & 7;
            cp16(sb + (r * GRS + s * 8) * 2, gA + (size_t)r * K + k0 + s * 8);
        }
        #pragma unroll
        for (int i = 0; i < 4; i++) {
            int idx = tid + i * 256;
            int r = idx >> 3, s = idx & 7;
            cp16(sb + ATB + (r * GRS + s * 8) * 2, gB + (size_t)r * K + k0 + s * 8);
        }
        asm volatile("cp.async.commit_group;");
    };

    const int laRowA = ((lane >> 3) & 1) * 8 + (lane & 7);
    const int laColA = (lane >> 4) * 8;
    const int laRowB = ((lane >> 4) << 3) + (lane & 7);
    const int laColB = ((lane >> 3) & 1) * 8;

    float c[4][4][4];
    #pragma unroll
    for (int i = 0; i < 4; i++)
        #pragma unroll
        for (int j = 0; j < 4; j++)
            #pragma unroll
            for (int q = 0; q < 4; q++) c[i][j][q] = 0.f;

    const int nch = K >> 6;
    stage(0, 0);
    stage(64, 1);

    // fragment double buffers
    uint32_t a[2][4][4];
    uint32_t bf[2][4][2];

    for (int ch = 0; ch < nch; ch++) {
        if (ch + 1 < nch) asm volatile("cp.async.wait_group 1;");
        else              asm volatile("cp.async.wait_group 0;");
        __syncthreads();
        if (ch + 2 < nch) stage((ch + 2) << 6, (ch + 2) % 3);

        const uint32_t sb = base + (ch % 3) * GSTAGE;
        const uint32_t sA = sb, sB = sb + ATB;

        auto ldfrags = [&](int ks, int pb) {
            #pragma unroll
            for (int mf = 0; mf < 4; mf++) {
                uint32_t off = ((wm * 64 + mf * 16 + laRowA) * GRS + ks + laColA) * 2;
                ldsm4(sA + off, a[pb][mf][0], a[pb][mf][1], a[pb][mf][2], a[pb][mf][3]);
            }
            #pragma unroll
            for (int np = 0; np < 2; np++) {
                uint32_t off = ((wn * 32 + np * 16 + laRowB) * GRS + ks + laColB) * 2;
                ldsm4(sB + off, bf[pb][2*np][0], bf[pb][2*np][1],
                                bf[pb][2*np+1][0], bf[pb][2*np+1][1]);
            }
        };

        ldfrags(0, 0);
        #pragma unroll
        for (int kk = 0; kk < 4; kk++) {
            const int pb = kk & 1;
            if (kk < 3) ldfrags((kk + 1) * 16, pb ^ 1);
            #pragma unroll
            for (int mf = 0; mf < 4; mf++)
                #pragma unroll
                for (int nf = 0; nf < 4; nf++)
                    mma_f16(c[mf][nf], a[pb][mf], bf[pb][nf][0], bf[pb][nf][1]);
        }
    }

    #pragma unroll
    for (int mf = 0; mf < 4; mf++) {
        const int rbase = m0 + wm * 64 + mf * 16 + (lane >> 2);
        #pragma unroll
        for (int nf = 0; nf < 4; nf++) {
            const int gn = n0 + wn * 32 + nf * 8 + (lane & 3) * 2;
            const float2 b2 = *(const float2*)(bias + gn);
            #pragma unroll
            for (int half_ = 0; half_ < 2; half_++) {
                const int gm = rbase + half_ * 8;
                float v0 = c[mf][nf][half_ * 2 + 0] + b2.x;
                float v1 = c[mf][nf][half_ * 2 + 1] + b2.y;
                if (GELU) { v0 = gelu_tanh(v0); v1 = gelu_tanh(v1); }
                if (OMODE == 0) {
                    if (res) {
                        const float2 r2 = *(const float2*)(res + (size_t)gm * N + gn);
                        v0 += r2.x; v1 += r2.y;
                    }
                    *(float2*)(outf + (size_t)gm * N + gn) = make_float2(v0, v1);
                } else {
                    *(uint32_t*)(outh + (size_t)gm * N + gn) =
                        pack2(__float2half(v0), __float2half(v1));
                }
            }
        }
    }
}

template<int OMODE, bool GELU>
__global__ __launch_bounds__(256, 2) void mma_gemm(
    const __half* __restrict__ Ah, const __half* __restrict__ Bh,
    const float* __restrict__ bias, const float* __restrict__ res,
    float* __restrict__ outf, __half* __restrict__ outh,
    int M, int N, int K)
{
    extern __shared__ __align__(16) char smem[];
    gemm_body<OMODE, GELU>(smem, Ah, Bh, bias, res, outf, outh, M, N, K,
                           blockIdx.y * 128, blockIdx.x * 128);
}

// Two independent fp16-out GEMMs fused into one launch (flattened 1D grid).
struct GemmDesc {
    const __half* A; const __half* B; const float* bias; __half* out;
    int M, N, K, gx, tiles;
};
__global__ __launch_bounds__(256, 2) void mma_gemm_pair(GemmDesc d0, GemmDesc d1)
{
    extern __shared__ __align__(16) char smem[];
    int bid = blockIdx.x;
    if (bid < d0.tiles) {
        gemm_body<1, false>(smem, d0.A, d0.B, d0.bias, nullptr, nullptr, d0.out,
                            d0.M, d0.N, d0.K, (bid / d0.gx) * 128, (bid % d0.gx) * 128);
    } else {
        bid -= d0.tiles;
        gemm_body<1, false>(smem, d1.A, d1.B, d1.bias, nullptr, nullptr, d1.out,
                            d1.M, d1.N, d1.K, (bid / d1.gx) * 128, (bid % d1.gx) * 128);
    }
}

// ---------------------------------------------------------------------------
// Flash attention, fp16 single-pass. BQ=128 (8 warps), BK=64, D=64.
// ---------------------------------------------------------------------------
#define FRS 72
#define QTB (128 * FRS * 2)
#define KVT (64 * FRS * 2)
#define KVSTAGE (2 * KVT)
#define FLASH_SMEM (QTB + 2 * KVSTAGE)

template<bool CAUSAL>
__global__ __launch_bounds__(256, 1) void flash_mma(
    const __half* __restrict__ Qh,
    const __half* __restrict__ Kh, const __half* __restrict__ Vh,
    __half* __restrict__ Ohi,
    int Tq, int Tkv, int qS, int kS, float scale)
{
    extern __shared__ __align__(16) char smem[];
    const uint32_t base = smem_u32(smem);
    const uint32_t sQ = base;

    const int tid = threadIdx.x;
    const int wid = tid >> 5, lane = tid & 31;
    const int bh = blockIdx.y;
    const int b = bh >> 4, h = bh & 15;
    const int qt = blockIdx.x;

    const __half* Qb  = Qh + (size_t)(b * Tq + qt * 128) * qS + h * 64;
    const __half* Khb = Kh + (size_t)(b * Tkv) * kS + h * 64;
    const __half* Vhb = Vh + (size_t)(b * Tkv) * kS + h * 64;

    auto stage_kv = [&](int kt, int buf) {
        const uint32_t sb = base + QTB + buf * KVSTAGE;
        #pragma unroll
        for (int i = 0; i < 2; i++) {
            int idx = tid + i * 256;
            int r = idx >> 3, s = idx & 7;
            size_t go = (size_t)(kt * 64 + r) * kS + s * 8;
            uint32_t off = (r * FRS + s * 8) * 2;
            cp16(sb + 0 * KVT + off, Khb + go);
            cp16(sb + 1 * KVT + off, Vhb + go);
        }
        asm volatile("cp.async.commit_group;");
    };

    #pragma unroll
    for (int i = 0; i < 4; i++) {
        int idx = tid + i * 256;
        int r = idx >> 3, s = idx & 7;
        cp16(sQ + (r * FRS + s * 8) * 2, Qb + (size_t)r * qS + s * 8);
    }
    stage_kv(0, 0);

    const int laRowA = ((lane >> 3) & 1) * 8 + (lane & 7);
    const int laColA = (lane >> 4) * 8;
    const int laRowB = ((lane >> 4) << 3) + (lane & 7);
    const int laColB = ((lane >> 3) & 1) * 8;

    float o[8][4];
    #pragma unroll
    for (int i = 0; i < 8; i++)
        #pragma unroll
        for (int j = 0; j < 4; j++) o[i][j] = 0.f;
    float mr0 = -1e30f, mr1 = -1e30f, lr0 = 0.f, lr1 = 0.f;

    const int nkt = CAUSAL ? (2 * qt + 2) : (Tkv >> 6);

    for (int kt = 0; kt < nkt; kt++) {
        if (kt + 1 < nkt) {
            stage_kv(kt + 1, (kt + 1) & 1);
            asm volatile("cp.async.wait_group 1;");
        } else {
            asm volatile("cp.async.wait_group 0;");
        }
        __syncthreads();

        const uint32_t sb = base + QTB + (kt & 1) * KVSTAGE;
        const uint32_t sK = sb, sV = sb + KVT;

        float s[8][4];
        #pragma unroll
        for (int i = 0; i < 8; i++)
            #pragma unroll
            for (int j = 0; j < 4; j++) s[i][j] = 0.f;

        #pragma unroll
        for (int ks = 0; ks < 4; ks++) {
            uint32_t q[4];
            uint32_t qoff = ((wid * 16 + laRowA) * FRS + ks * 16 + laColA) * 2;
            ldsm4(sQ + qoff, q[0], q[1], q[2], q[3]);
            #pragma unroll
            for (int np = 0; np < 4; np++) {
                uint32_t koff = ((np * 16 + laRowB) * FRS + ks * 16 + laColB) * 2;
                uint32_t k0, k1, k2, k3;
                ldsm4(sK + koff, k0, k1, k2, k3);
                mma_f16(s[2*np],   q, k0, k1);
                mma_f16(s[2*np+1], q, k2, k3);
            }
        }
        #pragma unroll
        for (int i = 0; i < 8; i++)
            #pragma unroll
            for (int j = 0; j < 4; j++) s[i][j] *= scale;

        if (CAUSAL && kt >= 2 * qt) {
            const int row0 = qt * 128 + wid * 16 + (lane >> 2);
            #pragma unroll
            for (int nf = 0; nf < 8; nf++) {
                const int col = kt * 64 + nf * 8 + (lane & 3) * 2;
                if (col     > row0)     s[nf][0] = -1e30f;
                if (col + 1 > row0)     s[nf][1] = -1e30f;
                if (col     > row0 + 8) s[nf][2] = -1e30f;
                if (col + 1 > row0 + 8) s[nf][3] = -1e30f;
            }
        }

        float t0 = -1e30f, t1 = -1e30f;
        #pragma unroll
        for (int nf = 0; nf < 8; nf++) {
            t0 = fmaxf(t0, fmaxf(s[nf][0], s[nf][1]));
            t1 = fmaxf(t1, fmaxf(s[nf][2], s[nf][3]));
        }
        t0 = fmaxf(t0, __shfl_xor_sync(0xffffffffu, t0, 1));
        t0 = fmaxf(t0, __shfl_xor_sync(0xffffffffu, t0, 2));
        t1 = fmaxf(t1, __shfl_xor_sync(0xffffffffu, t1, 1));
        t1 = fmaxf(t1, __shfl_xor_sync(0xffffffffu, t1, 2));
        const float nm0 = fmaxf(mr0, t0), nm1 = fmaxf(mr1, t1);
        const float f0 = __expf(mr0 - nm0), f1 = __expf(mr1 - nm1);
        mr0 = nm0; mr1 = nm1;

        float rs0 = 0.f, rs1 = 0.f;
        #pragma unroll
        for (int nf = 0; nf < 8; nf++) {
            s[nf][0] = __expf(s[nf][0] - nm0);
            s[nf][1] = __expf(s[nf][1] - nm0);
            s[nf][2] = __expf(s[nf][2] - nm1);
            s[nf][3] = __expf(s[nf][3] - nm1);
            rs0 += s[nf][0] + s[nf][1];
            rs1 += s[nf][2] + s[nf][3];
        }
        rs0 += __shfl_xor_sync(0xffffffffu, rs0, 1);
        rs0 += __shfl_xor_sync(0xffffffffu, rs0, 2);
        rs1 += __shfl_xor_sync(0xffffffffu, rs1, 1);
        rs1 += __shfl_xor_sync(0xffffffffu, rs1, 2);
        lr0 = lr0 * f0 + rs0;
        lr1 = lr1 * f1 + rs1;
        #pragma unroll
        for (int nf = 0; nf < 8; nf++) {
            o[nf][0] *= f0; o[nf][1] *= f0;
            o[nf][2] *= f1; o[nf][3] *= f1;
        }

        uint32_t ph[4][4];
        #pragma unroll
        for (int j = 0; j < 4; j++) {
            ph[j][0] = pack2(__float2half(s[2*j][0]),   __float2half(s[2*j][1]));
            ph[j][1] = pack2(__float2half(s[2*j][2]),   __float2half(s[2*j][3]));
            ph[j][2] = pack2(__float2half(s[2*j+1][0]), __float2half(s[2*j+1][1]));
            ph[j][3] = pack2(__float2half(s[2*j+1][2]), __float2half(s[2*j+1][3]));
        }

        #pragma unroll
        for (int j = 0; j < 4; j++) {
            #pragma unroll
            for (int np = 0; np < 4; np++) {
                uint32_t voff = ((j * 16 + laRowA) * FRS + np * 16 + laColA) * 2;
                uint32_t v0, v1, v2, v3;
                ldsm4t(sV + voff, v0, v1, v2, v3);
                mma_f16(o[2*np],   ph[j], v0, v1);
                mma_f16(o[2*np+1], ph[j], v2, v3);
            }
        }
        __syncthreads();
    }

    const float inv0 = 1.0f / lr0, inv1 = 1.0f / lr1;
    const int row0 = qt * 128 + wid * 16 + (lane >> 2);
    #pragma unroll
    for (int nf = 0; nf < 8; nf++) {
        const int col = h * 64 + nf * 8 + (lane & 3) * 2;
        {
            size_t off = (size_t)(b * Tq + row0) * CC + col;
            *(uint32_t*)(Ohi + off) =
                pack2(__float2half(o[nf][0] * inv0), __float2half(o[nf][1] * inv0));
        }
        {
            size_t off = (size_t)(b * Tq + row0 + 8) * CC + col;
            *(uint32_t*)(Ohi + off) =
                pack2(__float2half(o[nf][2] * inv1), __float2half(o[nf][3] * inv1));
        }
    }
}

// ---------------------------------------------------------------------------
// Launch sequence
// ---------------------------------------------------------------------------
extern "C" void kernel_launch(void* const* d_in, const int* in_sizes, int n_in,
                              void* d_out, int out_size)
{
    (void)in_sizes; (void)n_in; (void)out_size;
    const float* x      = (const float*)d_in[0];
    const float* ximg   = (const float*)d_in[1];
    const float* ln1_g  = (const float*)d_in[2];
    const float* ln1_b  = (const float*)d_in[3];
    const float* ln2_g  = (const float*)d_in[4];
    const float* ln2_b  = (const float*)d_in[5];
    const float* W_attn = (const float*)d_in[6];
    const float* b_attn = (const float*)d_in[7];
    const float* W_aproj= (const float*)d_in[8];
    const float* b_aproj= (const float*)d_in[9];
    const float* Wq     = (const float*)d_in[10];
    const float* bq     = (const float*)d_in[11];
    const float* Wk     = (const float*)d_in[12];
    const float* bk     = (const float*)d_in[13];
    const float* Wv     = (const float*)d_in[14];
    const float* bv     = (const float*)d_in[15];
    const float* Wcproj = (const float*)d_in[16];
    const float* bcproj = (const float*)d_in[17];
    const float* W_fc   = (const float*)d_in[18];
    const float* b_fc   = (const float*)d_in[19];
    const float* W_mproj= (const float*)d_in[20];
    const float* b_mproj= (const float*)d_in[21];
    float* out = (float*)d_out;

    __half *wt, *qkv, *q, *kv, *a, *ff, *xi;
    float* bkv;
    cudaGetSymbolAddress((void**)&wt,  g_wt);
    cudaGetSymbolAddress((void**)&qkv, g_qkv);
    cudaGetSymbolAddress((void**)&q,   g_q);
    cudaGetSymbolAddress((void**)&kv,  g_kv);
    cudaGetSymbolAddress((void**)&a,   g_a);
    cudaGetSymbolAddress((void**)&ff,  g_ff);
    cudaGetSymbolAddress((void**)&xi,  g_xi);
    cudaGetSymbolAddress((void**)&bkv, g_bkv);

    cudaFuncSetAttribute(mma_gemm<0,false>, cudaFuncAttributeMaxDynamicSharedMemorySize, GEMM_SMEM);
    cudaFuncSetAttribute(mma_gemm<1,false>, cudaFuncAttributeMaxDynamicSharedMemorySize, GEMM_SMEM);
    cudaFuncSetAttribute(mma_gemm<1,true>,  cudaFuncAttributeMaxDynamicSharedMemorySize, GEMM_SMEM);
    cudaFuncSetAttribute(mma_gemm_pair,     cudaFuncAttributeMaxDynamicSharedMemorySize, GEMM_SMEM);
    cudaFuncSetAttribute(flash_mma<true>,  cudaFuncAttributeMaxDynamicSharedMemorySize, FLASH_SMEM);
    cudaFuncSetAttribute(flash_mma<false>, cudaFuncAttributeMaxDynamicSharedMemorySize, FLASH_SMEM);

    const float scale = 0.125f;

    // ---- prep (ordered so the qkv GEMM is my-launch #3 → ncu capture) ----
    ln_h_kernel<<<MM, 256>>>(x, ln1_g, ln1_b, a);                              // 0
    Prep8 pp;
    pp.d[0] = { W_attn,  OFF_ATTN,  CC, 3*CC, (3*CC/32)*(CC/32) };
    pp.d[1] = { W_aproj, OFF_APROJ, CC, CC,   (CC/32)*(CC/32)   };
    pp.d[2] = { Wq,      OFF_Q,     CC, CC,   (CC/32)*(CC/32)   };
    pp.d[3] = { Wk,      OFF_K,     CC, CC,   (CC/32)*(CC/32)   };
    pp.d[4] = { Wv,      OFF_V,     CC, CC,   (CC/32)*(CC/32)   };
    pp.d[5] = { Wcproj,  OFF_CPROJ, CC, CC,   (CC/32)*(CC/32)   };
    pp.d[6] = { W_fc,    OFF_FC,    CC, FFD,  (FFD/32)*(CC/32)  };
    pp.d[7] = { W_mproj, OFF_MPROJ, FFD, CC,  (CC/32)*(FFD/32)  };
    prep_weights_kernel<<<3072 + 5*1024 + 2*4096, 256>>>(pp, wt);              // 1
    tofp16_kernel<<<(MIMG*CC + 255)/256, 256>>>(ximg, xi, MIMG*CC);            // 2

    // ---- causal self-attention ----
    mma_gemm<1,false><<<dim3(3*CC/128, MM/128), 256, GEMM_SMEM>>>(             // 3 (ncu)
        a, wt+OFF_ATTN, b_attn, nullptr, nullptr, qkv, MM, 3*CC, CC);
    concat_bias_kernel<<<(2*CC + 255)/256, 256>>>(bk, bv, bkv);                // 4
    flash_mma<true><<<dim3(8, 128), 256, FLASH_SMEM>>>(
        qkv, qkv + CC, qkv + 2*CC, a, 1024, 1024, 3*CC, 3*CC, scale);
    mma_gemm<0,false><<<dim3(CC/128, MM/128), 256, GEMM_SMEM>>>(
        a, wt+OFF_APROJ, b_aproj, x, out, nullptr, MM, CC, CC);

    // ---- cross-attention ----
    ln_h_kernel<<<MM, 256>>>(out, ln1_g, ln1_b, a);
    {
        GemmDesc d0 = { a,  wt+OFF_Q, bq,  q,  MM,   CC,   CC, CC/128,   (CC/128)*(MM/128)    };
        GemmDesc d1 = { xi, wt+OFF_K, bkv, kv, MIMG, 2*CC, CC, 2*CC/128, (2*CC/128)*(MIMG/128) };
        mma_gemm_pair<<<d0.tiles + d1.tiles, 256, GEMM_SMEM>>>(d0, d1);
    }
    flash_mma<false><<<dim3(8, 128), 256, FLASH_SMEM>>>(
        q, kv, kv + CC, a, 1024, 256, CC, 2*CC, scale);
    mma_gemm<0,false><<<dim3(CC/128, MM/128), 256, GEMM_SMEM>>>(
        a, wt+OFF_CPROJ, bcproj, out, out, nullptr, MM, CC, CC);

    // ---- MLP ----
    ln_h_kernel<<<MM, 256>>>(out, ln2_g, ln2_b, a);
    mma_gemm<1,true><<<dim3(FFD/128, MM/128), 256, GEMM_SMEM>>>(
        a, wt+OFF_FC, b_fc, nullptr, nullptr, ff, MM, FFD, CC);
    mma_gemm<0,false><<<dim3(CC/128, MM/128), 256, GEMM_SMEM>>>(
        ff, wt+OFF_MPROJ, b_mproj, out, out, nullptr, MM, CC, FFD);
}